// round 1
// baseline (speedup 1.0000x reference)
#include <cuda_runtime.h>
#include <cuda_bf16.h>

// Problem constants (from reference setup_inputs)
#define NFEAT 64
#define NHID  256
#define EMAX  320000
#define AMAX  10000
#define BAMAX 40000
#define EPS_F 0.1f
#define COEF0 0.31415926535897931f   // pi / R0, R0 = 10

typedef unsigned long long ull;

// ---------------- scratch (device globals; no allocation allowed) ------------
__device__ float g_buf1[(size_t)EMAX * NHID];   // 327 MB
__device__ float g_buf2[(size_t)EMAX * NHID];   // 327 MB
__device__ float g_abuf1[(size_t)BAMAX * NHID]; // 41 MB
__device__ float g_abuf2[(size_t)BAMAX * NHID]; // 41 MB
__device__ int   g_cnt[AMAX + 1];
__device__ int   g_off[AMAX + 1];
__device__ int   g_pos[AMAX];
__device__ int   g_elist[EMAX];

// ---------------- f32x2 helpers (Blackwell packed fp32 FMA) ------------------
__device__ __forceinline__ ull fpack2(float lo, float hi) {
    ull r; asm("mov.b64 %0, {%1,%2};" : "=l"(r) : "f"(lo), "f"(hi)); return r;
}
__device__ __forceinline__ void funpack2(ull v, float& lo, float& hi) {
    asm("mov.b64 {%0,%1}, %2;" : "=f"(lo), "=f"(hi) : "l"(v));
}
__device__ __forceinline__ ull ffma2(ull a, ull b, ull c) {
    ull d; asm("fma.rn.f32x2 %0, %1, %2, %3;" : "=l"(d) : "l"(a), "l"(b), "l"(c));
    return d;
}

// ---------------- radial encoding -------------------------------------------
// enc[e, j] : j<32 -> cos(c_j * |r|), j>=32 -> sin(c_{j-32} * |r|),
// c_k = (1 + k/2) * pi/10
__global__ void encode_kernel(const float* __restrict__ r_ij,
                              float* __restrict__ enc, int E) {
    int t = blockIdx.x * blockDim.x + threadIdx.x;
    if (t >= E * NFEAT) return;
    int e = t >> 6;
    int j = t & 63;
    float rx = __ldg(&r_ij[e * 3 + 0]);
    float ry = __ldg(&r_ij[e * 3 + 1]);
    float rz = __ldg(&r_ij[e * 3 + 2]);
    float d = sqrtf(rx * rx + ry * ry + rz * rz);
    int k = j & 31;
    float ph = (float)(1 + (k >> 1)) * COEF0 * d;
    enc[t] = (j < 32) ? cosf(ph) : sinf(ph);
}

// ---------------- SIMT fp32 GEMM with FFMA2: Y = act(X @ W + b) --------------
// X: MxK row-major, W: KxN (N=256) row-major, Y: Mx256. BM=128 BN=128 BK=16.
#define GBM 128
#define GBN 128
#define GBK 16

__global__ __launch_bounds__(256) void gemm_kernel(
    const float* __restrict__ X, const float* __restrict__ W,
    const float* __restrict__ bias, float* __restrict__ Y,
    int M, int K, int act)
{
    __shared__ float As[GBK][GBM + 4];  // transposed A tile: As[k][m]
    __shared__ float Bs[GBK][GBN];

    const int tid  = threadIdx.x;
    const int row0 = blockIdx.x * GBM;
    const int col0 = blockIdx.y * GBN;
    const int ty   = tid >> 4;
    const int tx   = tid & 15;
    const int trow = ty * 8;
    const int tcol = tx * 8;

    ull acc[8][4];
#pragma unroll
    for (int r = 0; r < 8; r++)
#pragma unroll
        for (int c = 0; c < 4; c++) acc[r][c] = 0ULL;

    // A-load mapping: float4 id f in [0,512): r = f>>2 (row), kq = f&3 (k quad)
    const int af0 = tid, af1 = tid + 256;
    const int ar0 = af0 >> 2, akq0 = af0 & 3;
    const int ar1 = af1 >> 2, akq1 = af1 & 3;
    // B-load mapping: f in [0,512): k = f>>5, n4 = f&31
    const int bk0 = af0 >> 5, bn0 = af0 & 31;
    const int bk1 = af1 >> 5, bn1 = af1 & 31;

    for (int kt = 0; kt < K; kt += GBK) {
        float4 a0 = make_float4(0.f, 0.f, 0.f, 0.f);
        float4 a1 = make_float4(0.f, 0.f, 0.f, 0.f);
        if (row0 + ar0 < M)
            a0 = *(const float4*)&X[(size_t)(row0 + ar0) * K + kt + akq0 * 4];
        if (row0 + ar1 < M)
            a1 = *(const float4*)&X[(size_t)(row0 + ar1) * K + kt + akq1 * 4];
        float4 b0 = *(const float4*)&W[(size_t)(kt + bk0) * 256 + col0 + bn0 * 4];
        float4 b1 = *(const float4*)&W[(size_t)(kt + bk1) * 256 + col0 + bn1 * 4];

        __syncthreads();
        As[akq0 * 4 + 0][ar0] = a0.x;
        As[akq0 * 4 + 1][ar0] = a0.y;
        As[akq0 * 4 + 2][ar0] = a0.z;
        As[akq0 * 4 + 3][ar0] = a0.w;
        As[akq1 * 4 + 0][ar1] = a1.x;
        As[akq1 * 4 + 1][ar1] = a1.y;
        As[akq1 * 4 + 2][ar1] = a1.z;
        As[akq1 * 4 + 3][ar1] = a1.w;
        *(float4*)&Bs[bk0][bn0 * 4] = b0;
        *(float4*)&Bs[bk1][bn1 * 4] = b1;
        __syncthreads();

#pragma unroll
        for (int kk = 0; kk < GBK; kk++) {
            float4 va0 = *(const float4*)&As[kk][trow];
            float4 va1 = *(const float4*)&As[kk][trow + 4];
            float4 vb0 = *(const float4*)&Bs[kk][tcol];
            float4 vb1 = *(const float4*)&Bs[kk][tcol + 4];
            ull bp0 = fpack2(vb0.x, vb0.y);
            ull bp1 = fpack2(vb0.z, vb0.w);
            ull bp2 = fpack2(vb1.x, vb1.y);
            ull bp3 = fpack2(vb1.z, vb1.w);
            float ar[8] = {va0.x, va0.y, va0.z, va0.w, va1.x, va1.y, va1.z, va1.w};
#pragma unroll
            for (int r = 0; r < 8; r++) {
                ull ad = fpack2(ar[r], ar[r]);
                acc[r][0] = ffma2(ad, bp0, acc[r][0]);
                acc[r][1] = ffma2(ad, bp1, acc[r][1]);
                acc[r][2] = ffma2(ad, bp2, acc[r][2]);
                acc[r][3] = ffma2(ad, bp3, acc[r][3]);
            }
        }
    }

    // epilogue: bias + optional SiLU, store
#pragma unroll
    for (int r = 0; r < 8; r++) {
        int row = row0 + trow + r;
        if (row >= M) continue;
        float o[8];
#pragma unroll
        for (int c = 0; c < 4; c++) funpack2(acc[r][c], o[2 * c], o[2 * c + 1]);
#pragma unroll
        for (int c = 0; c < 8; c++) {
            float v = o[c] + __ldg(&bias[col0 + tcol + c]);
            if (act) v = v / (1.f + __expf(-v));
            o[c] = v;
        }
        float* yp = &Y[(size_t)row * 256 + col0 + tcol];
        *(float4*)yp       = make_float4(o[0], o[1], o[2], o[3]);
        *(float4*)(yp + 4) = make_float4(o[4], o[5], o[6], o[7]);
    }
}

// ---------------- counting sort of edges by src ------------------------------
__global__ void zero_cnt_kernel(int A) {
    int t = blockIdx.x * blockDim.x + threadIdx.x;
    if (t <= A) g_cnt[t] = 0;
}
__global__ void hist_kernel(const int* __restrict__ src, int E) {
    int t = blockIdx.x * blockDim.x + threadIdx.x;
    if (t < E) atomicAdd(&g_cnt[src[t]], 1);
}
__global__ void scan_kernel(int A) {  // single block, 256 threads
    __shared__ int sh[256];
    int tid = threadIdx.x;
    int chunk = (A + 255) >> 8;
    int base = tid * chunk;
    int sum = 0;
    for (int j = 0; j < chunk; j++) {
        int idx = base + j;
        if (idx < A) sum += g_cnt[idx];
    }
    sh[tid] = sum;
    __syncthreads();
    for (int off = 1; off < 256; off <<= 1) {
        int v = 0;
        if (tid >= off) v = sh[tid - off];
        __syncthreads();
        sh[tid] += v;
        __syncthreads();
    }
    int run = (tid == 0) ? 0 : sh[tid - 1];
    for (int j = 0; j < chunk; j++) {
        int idx = base + j;
        if (idx < A) {
            g_off[idx] = run;
            g_pos[idx] = run;
            run += g_cnt[idx];
        }
    }
    if (base < A && A <= base + chunk) g_off[A] = run;
}
__global__ void scatter_kernel(const int* __restrict__ src, int E) {
    int t = blockIdx.x * blockDim.x + threadIdx.x;
    if (t < E) {
        int p = atomicAdd(&g_pos[src[t]], 1);
        g_elist[p] = t;
    }
}

// ---------------- per-atom gather (no float atomics) -------------------------
// block = atom a, 256 threads: i = tid&63 (feature), b = tid>>6 (batch)
__global__ __launch_bounds__(256) void gather_kernel(
    const float* __restrict__ dist, const float* __restrict__ actv,
    const float* __restrict__ x_v, const float* __restrict__ r_ij,
    const int* __restrict__ dst,
    float* __restrict__ out_a, float* __restrict__ out_v, int A)
{
    int a = blockIdx.x;
    int i = threadIdx.x & 63;
    int b = threadIdx.x >> 6;
    int p0 = g_off[a];
    int p1 = g_off[a + 1];

    float av0 = 0.f, av1 = 0.f, av2 = 0.f, aa = 0.f;
    for (int p = p0; p < p1; ++p) {
        int e = g_elist[p];
        float rx = __ldg(&r_ij[e * 3 + 0]);
        float ry = __ldg(&r_ij[e * 3 + 1]);
        float rz = __ldg(&r_ij[e * 3 + 2]);
        float inv = rsqrtf(EPS_F + rx * rx + ry * ry + rz * rz);
        float d0 = rx * inv, d1 = ry * inv, d2 = rz * inv;
        int dd = __ldg(&dst[e]);
        const float* D = dist + (size_t)e * 256;
        const float* P = actv + (size_t)(b * A + dd) * 256;
        float q0 = __ldg(&D[i])       * __ldg(&P[i]);
        float q1 = __ldg(&D[i + 64])  * __ldg(&P[i + 64]);
        float q2 = __ldg(&D[i + 128]) * __ldg(&P[i + 128]);
        float q3 = __ldg(&D[i + 192]) * __ldg(&P[i + 192]);
        const float* V = x_v + (size_t)((b * A + dd) * 64 + i) * 3;
        float v0 = __ldg(&V[0]), v1 = __ldg(&V[1]), v2 = __ldg(&V[2]);
        float c0 = v1 * d2 - v2 * d1;
        float c1 = v2 * d0 - v0 * d2;
        float c2 = v0 * d1 - v1 * d0;
        av0 += v0 * q0 + c0 * q1 + d0 * q2;
        av1 += v1 * q0 + c1 * q1 + d1 * q2;
        av2 += v2 * q0 + c2 * q1 + d2 * q2;
        aa  += q3;
    }
    out_a[(size_t)(b * A + a) * 64 + i] = aa;
    float* OV = out_v + (size_t)((b * A + a) * 64 + i) * 3;
    OV[0] = av0;
    OV[1] = av1;
    OV[2] = av2;
}

// ---------------- launch ------------------------------------------------------
extern "C" void kernel_launch(void* const* d_in, const int* in_sizes, int n_in,
                              void* d_out, int out_size) {
    const float* x_a  = (const float*)d_in[0];
    const float* x_v  = (const float*)d_in[1];
    const float* r_ij = (const float*)d_in[2];
    const int*   src  = (const int*)d_in[3];
    const int*   dst  = (const int*)d_in[4];
    const float* dW1 = (const float*)d_in[5];
    const float* db1 = (const float*)d_in[6];
    const float* dW2 = (const float*)d_in[7];
    const float* db2 = (const float*)d_in[8];
    const float* dW3 = (const float*)d_in[9];
    const float* db3 = (const float*)d_in[10];
    const float* aW1 = (const float*)d_in[11];
    const float* ab1 = (const float*)d_in[12];
    const float* aW2 = (const float*)d_in[13];
    const float* ab2 = (const float*)d_in[14];
    const float* aW3 = (const float*)d_in[15];
    const float* ab3 = (const float*)d_in[16];

    const int E  = in_sizes[3];           // src element count
    const int BA = in_sizes[0] / NFEAT;   // B * A
    const int A  = AMAX;                  // 10000 (problem constant)

    float *buf1, *buf2, *abuf1, *abuf2;
    cudaGetSymbolAddress((void**)&buf1, g_buf1);
    cudaGetSymbolAddress((void**)&buf2, g_buf2);
    cudaGetSymbolAddress((void**)&abuf1, g_abuf1);
    cudaGetSymbolAddress((void**)&abuf2, g_abuf2);

    // 1) radial encoding -> buf1[:E*64]
    encode_kernel<<<(E * NFEAT + 255) / 256, 256>>>(r_ij, buf1, E);

    // 2) dist MLP: enc -> buf2 -> buf1 -> buf2 (= dist_x_a, E x 256)
    dim3 gge((E + GBM - 1) / GBM, 2);
    gemm_kernel<<<gge, 256>>>(buf1, dW1, db1, buf2, E, 64, 1);
    gemm_kernel<<<gge, 256>>>(buf2, dW2, db2, buf1, E, 256, 1);
    gemm_kernel<<<gge, 256>>>(buf1, dW3, db3, buf2, E, 256, 0);

    // 3) actv MLP on atoms (commutes with dst gather): x_a -> abuf1 -> abuf2 -> abuf1
    dim3 gga((BA + GBM - 1) / GBM, 2);
    gemm_kernel<<<gga, 256>>>(x_a,  aW1, ab1, abuf1, BA, 64, 1);
    gemm_kernel<<<gga, 256>>>(abuf1, aW2, ab2, abuf2, BA, 256, 1);
    gemm_kernel<<<gga, 256>>>(abuf2, aW3, ab3, abuf1, BA, 256, 0);

    // 4) counting sort of edges by src
    zero_cnt_kernel<<<(A + 1 + 255) / 256, 256>>>(A);
    hist_kernel<<<(E + 255) / 256, 256>>>(src, E);
    scan_kernel<<<1, 256>>>(A);
    scatter_kernel<<<(E + 255) / 256, 256>>>(src, E);

    // 5) gather: one block per atom, registers accumulate, plain stores
    float* out_a = (float*)d_out;
    float* out_v = (float*)d_out + (size_t)BA * NFEAT;
    gather_kernel<<<A, 256>>>(buf2, abuf1, x_v, r_ij, dst, out_a, out_v, A);
}

// round 3
// speedup vs baseline: 1.5109x; 1.5109x over previous
#include <cuda_runtime.h>
#include <cuda_fp16.h>
#include <cstdint>

#define NFEAT 64
#define NHID  256
#define EMAX  320000
#define AMAX  10000
#define BAMAX 40000
#define EPS_F 0.1f
#define COEF0 0.31415926535897931f   // pi / R0, R0 = 10

// ---------------- scratch (device globals; no allocation allowed) ------------
__device__ __half g_h1[(size_t)EMAX * NHID];
__device__ __half g_l1[(size_t)EMAX * NHID];
__device__ __half g_h2[(size_t)EMAX * NHID];
__device__ __half g_l2[(size_t)EMAX * NHID];
__device__ float g_dist[(size_t)EMAX * NHID];   // final dist MLP output (fp32)
__device__ float g_actv[(size_t)BAMAX * NHID];  // final actv MLP output (fp32)
__device__ __half g_wh[6 * 256 * 256];          // transposed weight hi, 6 slots
__device__ __half g_wl[6 * 256 * 256];          // transposed weight lo
__device__ int g_cnt[AMAX + 1];
__device__ int g_off[AMAX + 1];
__device__ int g_pos[AMAX];
__device__ int g_elist[EMAX];

// ---------------- PTX helpers -------------------------------------------------
__device__ __forceinline__ uint32_t smem_u32(const void* p) {
    uint32_t a;
    asm("{ .reg .u64 t; cvta.to.shared.u64 t, %1; cvt.u32.u64 %0, t; }" : "=r"(a) : "l"(p));
    return a;
}
#define CP16(saddr, gptr) \
    asm volatile("cp.async.cg.shared.global [%0], [%1], 16;" :: "r"(saddr), "l"(gptr) : "memory")
#define CP_COMMIT asm volatile("cp.async.commit_group;" ::: "memory")
#define CP_WAIT0 asm volatile("cp.async.wait_group 0;" ::: "memory")
#define CP_WAIT1 asm volatile("cp.async.wait_group 1;" ::: "memory")

__device__ __forceinline__ void ldsm_x4(uint32_t* r, uint32_t addr) {
    asm volatile("ldmatrix.sync.aligned.m8n8.x4.shared.b16 {%0,%1,%2,%3}, [%4];"
                 : "=r"(r[0]), "=r"(r[1]), "=r"(r[2]), "=r"(r[3]) : "r"(addr));
}
__device__ __forceinline__ void mma16816(float* c, const uint32_t* a, uint32_t b0, uint32_t b1) {
    asm volatile("mma.sync.aligned.m16n8k16.row.col.f32.f16.f16.f32 "
                 "{%0,%1,%2,%3}, {%4,%5,%6,%7}, {%8,%9}, {%0,%1,%2,%3};"
                 : "+f"(c[0]), "+f"(c[1]), "+f"(c[2]), "+f"(c[3])
                 : "r"(a[0]), "r"(a[1]), "r"(a[2]), "r"(a[3]), "r"(b0), "r"(b1));
}
__device__ __forceinline__ void split_h(float v, __half& h, __half& l) {
    h = __float2half_rn(v);
    l = __float2half_rn(v - __half2float(h));
}

// ---------------- radial encoding -> fp16 hi/lo -------------------------------
__global__ void encode_kernel(const float* __restrict__ r_ij,
                              __half* __restrict__ eh, __half* __restrict__ el, int E) {
    int t = blockIdx.x * blockDim.x + threadIdx.x;
    if (t >= E * NFEAT) return;
    int e = t >> 6;
    int j = t & 63;
    float rx = __ldg(&r_ij[e * 3 + 0]);
    float ry = __ldg(&r_ij[e * 3 + 1]);
    float rz = __ldg(&r_ij[e * 3 + 2]);
    float d = sqrtf(rx * rx + ry * ry + rz * rz);
    int k = j & 31;
    float ph = (float)(1 + (k >> 1)) * COEF0 * d;
    float v = (j < 32) ? cosf(ph) : sinf(ph);
    __half h, l;
    split_h(v, h, l);
    eh[t] = h; el[t] = l;
}

__global__ void split_kernel(const float* __restrict__ x,
                             __half* __restrict__ xh, __half* __restrict__ xl, int n) {
    int t = blockIdx.x * blockDim.x + threadIdx.x;
    if (t >= n) return;
    __half h, l;
    split_h(x[t], h, l);
    xh[t] = h; xl[t] = l;
}

// weight transpose + split: W[K,256] fp32 -> Wt[256,K] fp16 hi/lo
__global__ void wtrans_kernel(const float* __restrict__ W, int K,
                              __half* __restrict__ wh, __half* __restrict__ wl) {
    int t = blockIdx.x * blockDim.x + threadIdx.x;
    if (t >= K * 256) return;
    int n = t & 255;
    int k = t >> 8;
    __half h, l;
    split_h(W[(size_t)k * 256 + n], h, l);
    wh[(size_t)n * K + k] = h;
    wl[(size_t)n * K + k] = l;
}

// ---------------- mma.sync fp16 split GEMM: Y = act(A @ Wt^T + b) -------------
// A: M x lda fp16 hi/lo. Wt: 256 x K fp16 hi/lo (K-major). Out N=256.
// CTA tile 128x128 (grid.y=2), 8 warps of 32x64, BK=64, 2-stage cp.async.
#define HBM_ 128
#define HBK 64
#define A_HI_OFF 0
#define A_LO_OFF 18432
#define B_HI_OFF 36864
#define B_LO_OFF 55296
#define STAGE_SZ 73728
#define ROWB 144   // 72 halves per row

__global__ __launch_bounds__(256) void hgemm_kernel(
    const __half* __restrict__ Ahi, const __half* __restrict__ Alo, int lda,
    const __half* __restrict__ Bhi, const __half* __restrict__ Blo,
    const float* __restrict__ bias,
    int M, int K, int act, int outf32,
    float* __restrict__ OutF,
    __half* __restrict__ OHi, __half* __restrict__ OLo)
{
    extern __shared__ char smem[];
    const uint32_t sbase = smem_u32(smem);
    const int tid = threadIdx.x;
    const int lane = tid & 31;
    const int wid = tid >> 5;
    const int warp_m = wid & 3;
    const int warp_n = wid >> 2;
    const int row0 = blockIdx.x * HBM_;
    const int col0 = blockIdx.y * 128;

    // ldmatrix per-lane byte offsets (within a stage)
    const uint32_t aoff = (uint32_t)(warp_m * 32 + (lane & 15)) * ROWB + ((lane >> 4) << 4);
    const uint32_t boff = (uint32_t)(warp_n * 64 + (lane & 7) + ((lane >> 4) << 3)) * ROWB
                        + (((lane >> 3) & 1) << 4);

    float acc[2][8][4];
#pragma unroll
    for (int tm = 0; tm < 2; tm++)
#pragma unroll
        for (int tn = 0; tn < 8; tn++)
#pragma unroll
            for (int j = 0; j < 4; j++) acc[tm][tn][j] = 0.f;

    const int NC = K / HBK;

    // ---- stage loader: 16 x 16B cp.async per thread -------------------------
    auto load_stage = [&](int buf, int kb) {
        const uint32_t sb = sbase + buf * STAGE_SZ;
#pragma unroll
        for (int it = 0; it < 4; it++) {
            int idx = tid + it * 256;
            int r = idx >> 3, cs = idx & 7;
            uint32_t so = (uint32_t)r * ROWB + cs * 16;
            size_t ga = (size_t)min(row0 + r, M - 1) * lda + kb + cs * 8;
            CP16(sb + A_HI_OFF + so, Ahi + ga);
            CP16(sb + A_LO_OFF + so, Alo + ga);
            size_t gb = (size_t)(col0 + r) * K + kb + cs * 8;
            CP16(sb + B_HI_OFF + so, Bhi + gb);
            CP16(sb + B_LO_OFF + so, Blo + gb);
        }
    };

    load_stage(0, 0);
    CP_COMMIT;
    if (NC > 1) { load_stage(1, HBK); CP_COMMIT; }

    for (int c = 0; c < NC; c++) {
        if (c + 1 < NC) { CP_WAIT1; } else { CP_WAIT0; }
        __syncthreads();
        const uint32_t sb = sbase + (c & 1) * STAGE_SZ;
        const uint32_t abase = sb + aoff;
        const uint32_t bbase = sb + B_HI_OFF + boff;
#pragma unroll
        for (int ks = 0; ks < 4; ks++) {
            uint32_t ah[2][4], al[2][4], bb[4][4];
            ldsm_x4(ah[0], abase + ks * 32);
            ldsm_x4(ah[1], abase + 16 * ROWB + ks * 32);
            ldsm_x4(al[0], abase + A_LO_OFF + ks * 32);
            ldsm_x4(al[1], abase + A_LO_OFF + 16 * ROWB + ks * 32);
#pragma unroll
            for (int tg = 0; tg < 4; tg++)
                ldsm_x4(bb[tg], bbase + tg * 16 * ROWB + ks * 32);
#pragma unroll
            for (int tm = 0; tm < 2; tm++)
#pragma unroll
                for (int tn = 0; tn < 8; tn++) {
                    uint32_t b0 = bb[tn >> 1][(tn & 1) * 2];
                    uint32_t b1 = bb[tn >> 1][(tn & 1) * 2 + 1];
                    mma16816(acc[tm][tn], ah[tm], b0, b1);
                    mma16816(acc[tm][tn], al[tm], b0, b1);
                }
#pragma unroll
            for (int tg = 0; tg < 4; tg++)
                ldsm_x4(bb[tg], bbase + (B_LO_OFF - B_HI_OFF) + tg * 16 * ROWB + ks * 32);
#pragma unroll
            for (int tm = 0; tm < 2; tm++)
#pragma unroll
                for (int tn = 0; tn < 8; tn++) {
                    uint32_t b0 = bb[tn >> 1][(tn & 1) * 2];
                    uint32_t b1 = bb[tn >> 1][(tn & 1) * 2 + 1];
                    mma16816(acc[tm][tn], ah[tm], b0, b1);
                }
        }
        if (c + 2 < NC) {
            __syncthreads();
            load_stage(c & 1, (c + 2) * HBK);
            CP_COMMIT;
        }
    }

    // ---- epilogue: bias + SiLU, fp32 or fp16 hi/lo stores --------------------
#pragma unroll
    for (int tm = 0; tm < 2; tm++)
#pragma unroll
        for (int tn = 0; tn < 8; tn++) {
            int r0 = row0 + warp_m * 32 + tm * 16 + (lane >> 2);
            int col = col0 + warp_n * 64 + tn * 8 + 2 * (lane & 3);
            float b0 = __ldg(&bias[col]);
            float b1 = __ldg(&bias[col + 1]);
            float v0 = acc[tm][tn][0] + b0;
            float v1 = acc[tm][tn][1] + b1;
            float v2 = acc[tm][tn][2] + b0;
            float v3 = acc[tm][tn][3] + b1;
            if (act) {
                v0 = v0 / (1.f + __expf(-v0));
                v1 = v1 / (1.f + __expf(-v1));
                v2 = v2 / (1.f + __expf(-v2));
                v3 = v3 / (1.f + __expf(-v3));
            }
            if (outf32) {
                if (r0 < M)     *(float2*)&OutF[(size_t)r0 * 256 + col]       = make_float2(v0, v1);
                if (r0 + 8 < M) *(float2*)&OutF[(size_t)(r0 + 8) * 256 + col] = make_float2(v2, v3);
            } else {
                __half h0, l0, h1, l1;
                if (r0 < M) {
                    split_h(v0, h0, l0); split_h(v1, h1, l1);
                    *(__half2*)&OHi[(size_t)r0 * 256 + col] = __halves2half2(h0, h1);
                    *(__half2*)&OLo[(size_t)r0 * 256 + col] = __halves2half2(l0, l1);
                }
                if (r0 + 8 < M) {
                    split_h(v2, h0, l0); split_h(v3, h1, l1);
                    *(__half2*)&OHi[(size_t)(r0 + 8) * 256 + col] = __halves2half2(h0, h1);
                    *(__half2*)&OLo[(size_t)(r0 + 8) * 256 + col] = __halves2half2(l0, l1);
                }
            }
        }
}

// ---------------- counting sort of edges by src ------------------------------
__global__ void zero_cnt_kernel(int A) {
    int t = blockIdx.x * blockDim.x + threadIdx.x;
    if (t <= A) g_cnt[t] = 0;
}
__global__ void hist_kernel(const int* __restrict__ src, int E) {
    int t = blockIdx.x * blockDim.x + threadIdx.x;
    if (t < E) atomicAdd(&g_cnt[src[t]], 1);
}
__global__ void scan_kernel(int A) {  // single block, 256 threads
    __shared__ int sh[256];
    int tid = threadIdx.x;
    int chunk = (A + 255) >> 8;
    int base = tid * chunk;
    int sum = 0;
    for (int j = 0; j < chunk; j++) {
        int idx = base + j;
        if (idx < A) sum += g_cnt[idx];
    }
    sh[tid] = sum;
    __syncthreads();
    for (int off = 1; off < 256; off <<= 1) {
        int v = 0;
        if (tid >= off) v = sh[tid - off];
        __syncthreads();
        sh[tid] += v;
        __syncthreads();
    }
    int run = (tid == 0) ? 0 : sh[tid - 1];
    for (int j = 0; j < chunk; j++) {
        int idx = base + j;
        if (idx < A) {
            g_off[idx] = run;
            g_pos[idx] = run;
            run += g_cnt[idx];
        }
    }
    if (base < A && A <= base + chunk) g_off[A] = run;
}
__global__ void scatter_kernel(const int* __restrict__ src, int E) {
    int t = blockIdx.x * blockDim.x + threadIdx.x;
    if (t < E) {
        int p = atomicAdd(&g_pos[src[t]], 1);
        g_elist[p] = t;
    }
}

// ---------------- per-atom gather (no float atomics) -------------------------
__global__ __launch_bounds__(256) void gather_kernel(
    const float* __restrict__ dist, const float* __restrict__ actv,
    const float* __restrict__ x_v, const float* __restrict__ r_ij,
    const int* __restrict__ dst,
    float* __restrict__ out_a, float* __restrict__ out_v, int A)
{
    int a = blockIdx.x;
    int i = threadIdx.x & 63;
    int b = threadIdx.x >> 6;
    int p0 = g_off[a];
    int p1 = g_off[a + 1];

    float av0 = 0.f, av1 = 0.f, av2 = 0.f, aa = 0.f;
    for (int p = p0; p < p1; ++p) {
        int e = g_elist[p];
        float rx = __ldg(&r_ij[e * 3 + 0]);
        float ry = __ldg(&r_ij[e * 3 + 1]);
        float rz = __ldg(&r_ij[e * 3 + 2]);
        float inv = rsqrtf(EPS_F + rx * rx + ry * ry + rz * rz);
        float d0 = rx * inv, d1 = ry * inv, d2 = rz * inv;
        int dd = __ldg(&dst[e]);
        const float* D = dist + (size_t)e * 256;
        const float* P = actv + (size_t)(b * A + dd) * 256;
        float q0 = __ldg(&D[i])       * __ldg(&P[i]);
        float q1 = __ldg(&D[i + 64])  * __ldg(&P[i + 64]);
        float q2 = __ldg(&D[i + 128]) * __ldg(&P[i + 128]);
        float q3 = __ldg(&D[i + 192]) * __ldg(&P[i + 192]);
        const float* V = x_v + (size_t)((b * A + dd) * 64 + i) * 3;
        float v0 = __ldg(&V[0]), v1 = __ldg(&V[1]), v2 = __ldg(&V[2]);
        float c0 = v1 * d2 - v2 * d1;
        float c1 = v2 * d0 - v0 * d2;
        float c2 = v0 * d1 - v1 * d0;
        av0 += v0 * q0 + c0 * q1 + d0 * q2;
        av1 += v1 * q0 + c1 * q1 + d1 * q2;
        av2 += v2 * q0 + c2 * q1 + d2 * q2;
        aa  += q3;
    }
    out_a[(size_t)(b * A + a) * 64 + i] = aa;
    float* OV = out_v + (size_t)((b * A + a) * 64 + i) * 3;
    OV[0] = av0;
    OV[1] = av1;
    OV[2] = av2;
}

// ---------------- launch ------------------------------------------------------
extern "C" void kernel_launch(void* const* d_in, const int* in_sizes, int n_in,
                              void* d_out, int out_size) {
    const float* x_a  = (const float*)d_in[0];
    const float* x_v  = (const float*)d_in[1];
    const float* r_ij = (const float*)d_in[2];
    const int*   src  = (const int*)d_in[3];
    const int*   dst  = (const int*)d_in[4];
    const float* dW1 = (const float*)d_in[5];
    const float* db1 = (const float*)d_in[6];
    const float* dW2 = (const float*)d_in[7];
    const float* db2 = (const float*)d_in[8];
    const float* dW3 = (const float*)d_in[9];
    const float* db3 = (const float*)d_in[10];
    const float* aW1 = (const float*)d_in[11];
    const float* ab1 = (const float*)d_in[12];
    const float* aW2 = (const float*)d_in[13];
    const float* ab2 = (const float*)d_in[14];
    const float* aW3 = (const float*)d_in[15];
    const float* ab3 = (const float*)d_in[16];

    const int E  = in_sizes[3];
    const int BA = in_sizes[0] / NFEAT;
    const int A  = AMAX;

    __half *h1, *l1, *h2, *l2, *wh, *wl;
    float *dist, *actv;
    cudaGetSymbolAddress((void**)&h1, g_h1);
    cudaGetSymbolAddress((void**)&l1, g_l1);
    cudaGetSymbolAddress((void**)&h2, g_h2);
    cudaGetSymbolAddress((void**)&l2, g_l2);
    cudaGetSymbolAddress((void**)&wh, g_wh);
    cudaGetSymbolAddress((void**)&wl, g_wl);
    cudaGetSymbolAddress((void**)&dist, g_dist);
    cudaGetSymbolAddress((void**)&actv, g_actv);

    cudaFuncSetAttribute(hgemm_kernel, cudaFuncAttributeMaxDynamicSharedMemorySize, 2 * STAGE_SZ);

    const int SLOT = 256 * 256;
    wtrans_kernel<<<(64  * 256 + 255) / 256, 256>>>(dW1, 64,  wh + 0 * SLOT, wl + 0 * SLOT);
    wtrans_kernel<<<(256 * 256 + 255) / 256, 256>>>(dW2, 256, wh + 1 * SLOT, wl + 1 * SLOT);
    wtrans_kernel<<<(256 * 256 + 255) / 256, 256>>>(dW3, 256, wh + 2 * SLOT, wl + 2 * SLOT);
    wtrans_kernel<<<(64  * 256 + 255) / 256, 256>>>(aW1, 64,  wh + 3 * SLOT, wl + 3 * SLOT);
    wtrans_kernel<<<(256 * 256 + 255) / 256, 256>>>(aW2, 256, wh + 4 * SLOT, wl + 4 * SLOT);
    wtrans_kernel<<<(256 * 256 + 255) / 256, 256>>>(aW3, 256, wh + 5 * SLOT, wl + 5 * SLOT);

    // dist MLP: encode -> (h1,l1) -> (h2,l2) -> (h1,l1) -> g_dist
    encode_kernel<<<(E * NFEAT + 255) / 256, 256>>>(r_ij, h1, l1, E);
    dim3 gge((E + HBM_ - 1) / HBM_, 2);
    hgemm_kernel<<<gge, 256, 2 * STAGE_SZ>>>(h1, l1, 64,  wh + 0 * SLOT, wl + 0 * SLOT, db1, E, 64,  1, 0, nullptr, h2, l2);
    hgemm_kernel<<<gge, 256, 2 * STAGE_SZ>>>(h2, l2, 256, wh + 1 * SLOT, wl + 1 * SLOT, db2, E, 256, 1, 0, nullptr, h1, l1);
    hgemm_kernel<<<gge, 256, 2 * STAGE_SZ>>>(h1, l1, 256, wh + 2 * SLOT, wl + 2 * SLOT, db3, E, 256, 0, 1, dist, nullptr, nullptr);

    // actv MLP on atoms: x_a -> (h2,l2) -> (h1,l1) -> (h2,l2) -> g_actv
    split_kernel<<<(BA * NFEAT + 255) / 256, 256>>>(x_a, h2, l2, BA * NFEAT);
    dim3 gga((BA + HBM_ - 1) / HBM_, 2);
    hgemm_kernel<<<gga, 256, 2 * STAGE_SZ>>>(h2, l2, 64,  wh + 3 * SLOT, wl + 3 * SLOT, ab1, BA, 64,  1, 0, nullptr, h1, l1);
    hgemm_kernel<<<gga, 256, 2 * STAGE_SZ>>>(h1, l1, 256, wh + 4 * SLOT, wl + 4 * SLOT, ab2, BA, 256, 1, 0, nullptr, h2, l2);
    hgemm_kernel<<<gga, 256, 2 * STAGE_SZ>>>(h2, l2, 256, wh + 5 * SLOT, wl + 5 * SLOT, ab3, BA, 256, 0, 1, actv, nullptr, nullptr);

    // counting sort of edges by src
    zero_cnt_kernel<<<(A + 1 + 255) / 256, 256>>>(A);
    hist_kernel<<<(E + 255) / 256, 256>>>(src, E);
    scan_kernel<<<1, 256>>>(A);
    scatter_kernel<<<(E + 255) / 256, 256>>>(src, E);

    // gather
    float* out_a = (float*)d_out;
    float* out_v = (float*)d_out + (size_t)BA * NFEAT;
    gather_kernel<<<A, 256>>>(dist, actv, x_v, r_ij, dst, out_a, out_v, A);
}

// round 4
// speedup vs baseline: 4.4182x; 2.9242x over previous
#include <cuda_runtime.h>
#include <cuda_fp16.h>
#include <cstdint>

#define NFEAT 64
#define NHID  256
#define EMAX  320000
#define AMAX  10000
#define BAMAX 40000
#define EPS_F 0.1f
#define COEF0 0.31415926535897931f   // pi / R0, R0 = 10
#define NTAB  16384
#define DMAX  10.0f
#define TSCALE ((float)NTAB / DMAX)

// ---------------- scratch (device globals; no allocation allowed) ------------
__device__ __half g_h1[(size_t)BAMAX * NHID];
__device__ __half g_l1[(size_t)BAMAX * NHID];
__device__ __half g_h2[(size_t)BAMAX * NHID];
__device__ __half g_l2[(size_t)BAMAX * NHID];
__device__ float  g_table[(size_t)NTAB * NHID];   // dist MLP lookup, [k][feat][4] perm
__device__ __half g_actvh[(size_t)BAMAX * NHID];  // actv MLP out, [row][feat][4] perm
__device__ __half g_wh[6 * 256 * 256];
__device__ __half g_wl[6 * 256 * 256];
__device__ int g_cnt[AMAX + 1];
__device__ int g_off[AMAX + 1];
__device__ int g_pos[AMAX];
__device__ int g_elist[EMAX];

// ---------------- PTX helpers -------------------------------------------------
__device__ __forceinline__ uint32_t smem_u32(const void* p) {
    uint32_t a;
    asm("{ .reg .u64 t; cvta.to.shared.u64 t, %1; cvt.u32.u64 %0, t; }" : "=r"(a) : "l"(p));
    return a;
}
#define CP16(saddr, gptr) \
    asm volatile("cp.async.cg.shared.global [%0], [%1], 16;" :: "r"(saddr), "l"(gptr) : "memory")
#define CP_COMMIT asm volatile("cp.async.commit_group;" ::: "memory")
#define CP_WAIT0 asm volatile("cp.async.wait_group 0;" ::: "memory")
#define CP_WAIT1 asm volatile("cp.async.wait_group 1;" ::: "memory")

__device__ __forceinline__ void ldsm_x4(uint32_t* r, uint32_t addr) {
    asm volatile("ldmatrix.sync.aligned.m8n8.x4.shared.b16 {%0,%1,%2,%3}, [%4];"
                 : "=r"(r[0]), "=r"(r[1]), "=r"(r[2]), "=r"(r[3]) : "r"(addr));
}
__device__ __forceinline__ void mma16816(float* c, const uint32_t* a, uint32_t b0, uint32_t b1) {
    asm volatile("mma.sync.aligned.m16n8k16.row.col.f32.f16.f16.f32 "
                 "{%0,%1,%2,%3}, {%4,%5,%6,%7}, {%8,%9}, {%0,%1,%2,%3};"
                 : "+f"(c[0]), "+f"(c[1]), "+f"(c[2]), "+f"(c[3])
                 : "r"(a[0]), "r"(a[1]), "r"(a[2]), "r"(a[3]), "r"(b0), "r"(b1));
}
__device__ __forceinline__ void split_h(float v, __half& h, __half& l) {
    h = __float2half_rn(v);
    l = __float2half_rn(v - __half2float(h));
}

// ---------------- table encode: radial_encode at d = k * (DMAX/NTAB) ----------
__global__ void tencode_kernel(__half* __restrict__ eh, __half* __restrict__ el) {
    int t = blockIdx.x * blockDim.x + threadIdx.x;
    if (t >= NTAB * NFEAT) return;
    int k = t >> 6;
    int j = t & 63;
    float d = (float)k * (DMAX / (float)NTAB);
    int kk = j & 31;
    float ph = (float)(1 + (kk >> 1)) * COEF0 * d;
    float v = (j < 32) ? cosf(ph) : sinf(ph);
    __half h, l;
    split_h(v, h, l);
    eh[t] = h; el[t] = l;
}

__global__ void split_kernel(const float* __restrict__ x,
                             __half* __restrict__ xh, __half* __restrict__ xl, int n) {
    int t = blockIdx.x * blockDim.x + threadIdx.x;
    if (t >= n) return;
    __half h, l;
    split_h(x[t], h, l);
    xh[t] = h; xl[t] = l;
}

// weight transpose + split: W[K,256] fp32 -> Wt[256,K] fp16 hi/lo
__global__ void wtrans_kernel(const float* __restrict__ W, int K,
                              __half* __restrict__ wh, __half* __restrict__ wl) {
    int t = blockIdx.x * blockDim.x + threadIdx.x;
    if (t >= K * 256) return;
    int n = t & 255;
    int k = t >> 8;
    __half h, l;
    split_h(W[(size_t)k * 256 + n], h, l);
    wh[(size_t)n * K + k] = h;
    wl[(size_t)n * K + k] = l;
}

// ---------------- mma.sync fp16 split GEMM: Y = act(A @ Wt^T + b) -------------
// mode 0: fp16 hi/lo out; mode 1: fp32 permuted out; mode 2: fp16 permuted out
#define HBM_ 128
#define HBK 64
#define A_HI_OFF 0
#define A_LO_OFF 18432
#define B_HI_OFF 36864
#define B_LO_OFF 55296
#define STAGE_SZ 73728
#define ROWB 144   // 72 halves per row

__global__ __launch_bounds__(256) void hgemm_kernel(
    const __half* __restrict__ Ahi, const __half* __restrict__ Alo, int lda,
    const __half* __restrict__ Bhi, const __half* __restrict__ Blo,
    const float* __restrict__ bias,
    int M, int K, int act, int mode,
    float* __restrict__ OutF,
    __half* __restrict__ OHi, __half* __restrict__ OLo)
{
    extern __shared__ char smem[];
    const uint32_t sbase = smem_u32(smem);
    const int tid = threadIdx.x;
    const int lane = tid & 31;
    const int wid = tid >> 5;
    const int warp_m = wid & 3;
    const int warp_n = wid >> 2;
    const int row0 = blockIdx.x * HBM_;
    const int col0 = blockIdx.y * 128;

    const uint32_t aoff = (uint32_t)(warp_m * 32 + (lane & 15)) * ROWB + ((lane >> 4) << 4);
    const uint32_t boff = (uint32_t)(warp_n * 64 + (lane & 7) + ((lane >> 4) << 3)) * ROWB
                        + (((lane >> 3) & 1) << 4);

    float acc[2][8][4];
#pragma unroll
    for (int tm = 0; tm < 2; tm++)
#pragma unroll
        for (int tn = 0; tn < 8; tn++)
#pragma unroll
            for (int j = 0; j < 4; j++) acc[tm][tn][j] = 0.f;

    const int NC = K / HBK;

    auto load_stage = [&](int buf, int kb) {
        const uint32_t sb = sbase + buf * STAGE_SZ;
#pragma unroll
        for (int it = 0; it < 4; it++) {
            int idx = tid + it * 256;
            int r = idx >> 3, cs = idx & 7;
            uint32_t so = (uint32_t)r * ROWB + cs * 16;
            size_t ga = (size_t)min(row0 + r, M - 1) * lda + kb + cs * 8;
            CP16(sb + A_HI_OFF + so, Ahi + ga);
            CP16(sb + A_LO_OFF + so, Alo + ga);
            size_t gb = (size_t)(col0 + r) * K + kb + cs * 8;
            CP16(sb + B_HI_OFF + so, Bhi + gb);
            CP16(sb + B_LO_OFF + so, Blo + gb);
        }
    };

    load_stage(0, 0);
    CP_COMMIT;
    if (NC > 1) { load_stage(1, HBK); CP_COMMIT; }

    for (int c = 0; c < NC; c++) {
        if (c + 1 < NC) { CP_WAIT1; } else { CP_WAIT0; }
        __syncthreads();
        const uint32_t sb = sbase + (c & 1) * STAGE_SZ;
        const uint32_t abase = sb + aoff;
        const uint32_t bbase = sb + B_HI_OFF + boff;
#pragma unroll
        for (int ks = 0; ks < 4; ks++) {
            uint32_t ah[2][4], al[2][4], bb[4][4];
            ldsm_x4(ah[0], abase + ks * 32);
            ldsm_x4(ah[1], abase + 16 * ROWB + ks * 32);
            ldsm_x4(al[0], abase + A_LO_OFF + ks * 32);
            ldsm_x4(al[1], abase + A_LO_OFF + 16 * ROWB + ks * 32);
#pragma unroll
            for (int tg = 0; tg < 4; tg++)
                ldsm_x4(bb[tg], bbase + tg * 16 * ROWB + ks * 32);
#pragma unroll
            for (int tm = 0; tm < 2; tm++)
#pragma unroll
                for (int tn = 0; tn < 8; tn++) {
                    uint32_t b0 = bb[tn >> 1][(tn & 1) * 2];
                    uint32_t b1 = bb[tn >> 1][(tn & 1) * 2 + 1];
                    mma16816(acc[tm][tn], ah[tm], b0, b1);
                    mma16816(acc[tm][tn], al[tm], b0, b1);
                }
#pragma unroll
            for (int tg = 0; tg < 4; tg++)
                ldsm_x4(bb[tg], bbase + (B_LO_OFF - B_HI_OFF) + tg * 16 * ROWB + ks * 32);
#pragma unroll
            for (int tm = 0; tm < 2; tm++)
#pragma unroll
                for (int tn = 0; tn < 8; tn++) {
                    uint32_t b0 = bb[tn >> 1][(tn & 1) * 2];
                    uint32_t b1 = bb[tn >> 1][(tn & 1) * 2 + 1];
                    mma16816(acc[tm][tn], ah[tm], b0, b1);
                }
        }
        if (c + 2 < NC) {
            __syncthreads();
            load_stage(c & 1, (c + 2) * HBK);
            CP_COMMIT;
        }
    }

#pragma unroll
    for (int tm = 0; tm < 2; tm++)
#pragma unroll
        for (int tn = 0; tn < 8; tn++) {
            int r0 = row0 + warp_m * 32 + tm * 16 + (lane >> 2);
            int col = col0 + warp_n * 64 + tn * 8 + 2 * (lane & 3);
            float b0 = __ldg(&bias[col]);
            float b1 = __ldg(&bias[col + 1]);
            float v0 = acc[tm][tn][0] + b0;
            float v1 = acc[tm][tn][1] + b1;
            float v2 = acc[tm][tn][2] + b0;
            float v3 = acc[tm][tn][3] + b1;
            if (act) {
                v0 = v0 / (1.f + __expf(-v0));
                v1 = v1 / (1.f + __expf(-v1));
                v2 = v2 / (1.f + __expf(-v2));
                v3 = v3 / (1.f + __expf(-v3));
            }
            if (mode == 0) {
                __half h0, l0, h1, l1;
                if (r0 < M) {
                    split_h(v0, h0, l0); split_h(v1, h1, l1);
                    *(__half2*)&OHi[(size_t)r0 * 256 + col] = __halves2half2(h0, h1);
                    *(__half2*)&OLo[(size_t)r0 * 256 + col] = __halves2half2(l0, l1);
                }
                if (r0 + 8 < M) {
                    split_h(v2, h0, l0); split_h(v3, h1, l1);
                    *(__half2*)&OHi[(size_t)(r0 + 8) * 256 + col] = __halves2half2(h0, h1);
                    *(__half2*)&OLo[(size_t)(r0 + 8) * 256 + col] = __halves2half2(l0, l1);
                }
            } else {
                // permuted column: col -> (col & 63) * 4 + (col >> 6)
                int pc0 = ((col & 63) << 2) | (col >> 6);
                int pc1 = (((col + 1) & 63) << 2) | ((col + 1) >> 6);
                if (mode == 1) {
                    if (r0 < M) {
                        OutF[(size_t)r0 * 256 + pc0] = v0;
                        OutF[(size_t)r0 * 256 + pc1] = v1;
                    }
                    if (r0 + 8 < M) {
                        OutF[(size_t)(r0 + 8) * 256 + pc0] = v2;
                        OutF[(size_t)(r0 + 8) * 256 + pc1] = v3;
                    }
                } else {
                    if (r0 < M) {
                        OHi[(size_t)r0 * 256 + pc0] = __float2half_rn(v0);
                        OHi[(size_t)r0 * 256 + pc1] = __float2half_rn(v1);
                    }
                    if (r0 + 8 < M) {
                        OHi[(size_t)(r0 + 8) * 256 + pc0] = __float2half_rn(v2);
                        OHi[(size_t)(r0 + 8) * 256 + pc1] = __float2half_rn(v3);
                    }
                }
            }
        }
}

// ---------------- counting sort of edges by src ------------------------------
__global__ void zero_cnt_kernel(int A) {
    int t = blockIdx.x * blockDim.x + threadIdx.x;
    if (t <= A) g_cnt[t] = 0;
}
__global__ void hist_kernel(const int* __restrict__ src, int E) {
    int t = blockIdx.x * blockDim.x + threadIdx.x;
    if (t < E) atomicAdd(&g_cnt[src[t]], 1);
}
__global__ void scan_kernel(int A) {
    __shared__ int sh[256];
    int tid = threadIdx.x;
    int chunk = (A + 255) >> 8;
    int base = tid * chunk;
    int sum = 0;
    for (int j = 0; j < chunk; j++) {
        int idx = base + j;
        if (idx < A) sum += g_cnt[idx];
    }
    sh[tid] = sum;
    __syncthreads();
    for (int off = 1; off < 256; off <<= 1) {
        int v = 0;
        if (tid >= off) v = sh[tid - off];
        __syncthreads();
        sh[tid] += v;
        __syncthreads();
    }
    int run = (tid == 0) ? 0 : sh[tid - 1];
    for (int j = 0; j < chunk; j++) {
        int idx = base + j;
        if (idx < A) {
            g_off[idx] = run;
            g_pos[idx] = run;
            run += g_cnt[idx];
        }
    }
    if (base < A && A <= base + chunk) g_off[A] = run;
}
__global__ void scatter_kernel(const int* __restrict__ src, int E) {
    int t = blockIdx.x * blockDim.x + threadIdx.x;
    if (t < E) {
        int p = atomicAdd(&g_pos[src[t]], 1);
        g_elist[p] = t;
    }
}

// ---------------- per-atom gather with in-loop table lerp --------------------
// block = atom a; 256 threads: f = tid&63 (feature), b = tid>>6 (batch)
__global__ __launch_bounds__(256) void gather_kernel(
    const float4* __restrict__ T4,          // g_table as [k][feat] float4 (roles)
    const uint2* __restrict__ P4,           // g_actvh as [row][feat] 4x half (roles)
    const float* __restrict__ x_v, const float* __restrict__ r_ij,
    const int* __restrict__ dst,
    float* __restrict__ out_a, float* __restrict__ out_v, int A)
{
    int a = blockIdx.x;
    int f = threadIdx.x & 63;
    int b = threadIdx.x >> 6;
    int p0 = g_off[a];
    int p1 = g_off[a + 1];

    float av0 = 0.f, av1 = 0.f, av2 = 0.f, aa = 0.f;
    for (int p = p0; p < p1; ++p) {
        int e = g_elist[p];
        float rx = __ldg(&r_ij[e * 3 + 0]);
        float ry = __ldg(&r_ij[e * 3 + 1]);
        float rz = __ldg(&r_ij[e * 3 + 2]);
        float d2s = rx * rx + ry * ry + rz * rz;
        float d = sqrtf(d2s);
        float inv = rsqrtf(EPS_F + d2s);
        float d0 = rx * inv, d1 = ry * inv, d2 = rz * inv;

        float idxf = d * TSCALE;
        int k = (int)idxf;
        if (k > NTAB - 2) k = NTAB - 2;
        float w = idxf - (float)k;
        if (w > 1.f) w = 1.f;

        float4 t0 = __ldg(&T4[(size_t)k * 64 + f]);
        float4 t1 = __ldg(&T4[(size_t)(k + 1) * 64 + f]);
        float q0 = fmaf(w, t1.x - t0.x, t0.x);
        float q1 = fmaf(w, t1.y - t0.y, t0.y);
        float q2 = fmaf(w, t1.z - t0.z, t0.z);
        float q3 = fmaf(w, t1.w - t0.w, t0.w);

        int dd = __ldg(&dst[e]);
        uint2 pr = __ldg(&P4[(size_t)(b * A + dd) * 64 + f]);
        __half2 pa = *(__half2*)&pr.x;
        __half2 pb = *(__half2*)&pr.y;
        q0 *= __low2float(pa);
        q1 *= __high2float(pa);
        q2 *= __low2float(pb);
        q3 *= __high2float(pb);

        const float* V = x_v + (size_t)((b * A + dd) * 64 + f) * 3;
        float v0 = __ldg(&V[0]), v1 = __ldg(&V[1]), v2 = __ldg(&V[2]);
        float c0 = v1 * d2 - v2 * d1;
        float c1 = v2 * d0 - v0 * d2;
        float c2 = v0 * d1 - v1 * d0;
        av0 += v0 * q0 + c0 * q1 + d0 * q2;
        av1 += v1 * q0 + c1 * q1 + d1 * q2;
        av2 += v2 * q0 + c2 * q1 + d2 * q2;
        aa  += q3;
    }
    out_a[(size_t)(b * A + a) * 64 + f] = aa;
    float* OV = out_v + (size_t)((b * A + a) * 64 + f) * 3;
    OV[0] = av0;
    OV[1] = av1;
    OV[2] = av2;
}

// ---------------- launch ------------------------------------------------------
extern "C" void kernel_launch(void* const* d_in, const int* in_sizes, int n_in,
                              void* d_out, int out_size) {
    const float* x_a  = (const float*)d_in[0];
    const float* x_v  = (const float*)d_in[1];
    const float* r_ij = (const float*)d_in[2];
    const int*   src  = (const int*)d_in[3];
    const int*   dst  = (const int*)d_in[4];
    const float* dW1 = (const float*)d_in[5];
    const float* db1 = (const float*)d_in[6];
    const float* dW2 = (const float*)d_in[7];
    const float* db2 = (const float*)d_in[8];
    const float* dW3 = (const float*)d_in[9];
    const float* db3 = (const float*)d_in[10];
    const float* aW1 = (const float*)d_in[11];
    const float* ab1 = (const float*)d_in[12];
    const float* aW2 = (const float*)d_in[13];
    const float* ab2 = (const float*)d_in[14];
    const float* aW3 = (const float*)d_in[15];
    const float* ab3 = (const float*)d_in[16];

    const int E  = in_sizes[3];
    const int BA = in_sizes[0] / NFEAT;
    const int A  = BA / 4;                 // B = 4

    __half *h1, *l1, *h2, *l2, *wh, *wl, *actvh;
    float *table;
    cudaGetSymbolAddress((void**)&h1, g_h1);
    cudaGetSymbolAddress((void**)&l1, g_l1);
    cudaGetSymbolAddress((void**)&h2, g_h2);
    cudaGetSymbolAddress((void**)&l2, g_l2);
    cudaGetSymbolAddress((void**)&wh, g_wh);
    cudaGetSymbolAddress((void**)&wl, g_wl);
    cudaGetSymbolAddress((void**)&table, g_table);
    cudaGetSymbolAddress((void**)&actvh, g_actvh);

    cudaFuncSetAttribute(hgemm_kernel, cudaFuncAttributeMaxDynamicSharedMemorySize, 2 * STAGE_SZ);

    const int SLOT = 256 * 256;
    wtrans_kernel<<<(64  * 256 + 255) / 256, 256>>>(dW1, 64,  wh + 0 * SLOT, wl + 0 * SLOT);
    wtrans_kernel<<<(256 * 256 + 255) / 256, 256>>>(dW2, 256, wh + 1 * SLOT, wl + 1 * SLOT);
    wtrans_kernel<<<(256 * 256 + 255) / 256, 256>>>(dW3, 256, wh + 2 * SLOT, wl + 2 * SLOT);
    wtrans_kernel<<<(64  * 256 + 255) / 256, 256>>>(aW1, 64,  wh + 3 * SLOT, wl + 3 * SLOT);
    wtrans_kernel<<<(256 * 256 + 255) / 256, 256>>>(aW2, 256, wh + 4 * SLOT, wl + 4 * SLOT);
    wtrans_kernel<<<(256 * 256 + 255) / 256, 256>>>(aW3, 256, wh + 5 * SLOT, wl + 5 * SLOT);

    // dist MLP lookup table: tencode -> (h1,l1) -> (h2,l2) -> (h1,l1) -> g_table (fp32 perm)
    tencode_kernel<<<(NTAB * NFEAT + 255) / 256, 256>>>(h1, l1);
    dim3 ggt(NTAB / HBM_, 2);
    hgemm_kernel<<<ggt, 256, 2 * STAGE_SZ>>>(h1, l1, 64,  wh + 0 * SLOT, wl + 0 * SLOT, db1, NTAB, 64,  1, 0, nullptr, h2, l2);
    hgemm_kernel<<<ggt, 256, 2 * STAGE_SZ>>>(h2, l2, 256, wh + 1 * SLOT, wl + 1 * SLOT, db2, NTAB, 256, 1, 0, nullptr, h1, l1);
    hgemm_kernel<<<ggt, 256, 2 * STAGE_SZ>>>(h1, l1, 256, wh + 2 * SLOT, wl + 2 * SLOT, db3, NTAB, 256, 0, 1, table, nullptr, nullptr);

    // actv MLP on atoms: x_a -> (h2,l2) -> (h1,l1) -> (h2,l2) -> g_actvh (fp16 perm)
    split_kernel<<<(BA * NFEAT + 255) / 256, 256>>>(x_a, h2, l2, BA * NFEAT);
    dim3 gga((BA + HBM_ - 1) / HBM_, 2);
    hgemm_kernel<<<gga, 256, 2 * STAGE_SZ>>>(h2, l2, 64,  wh + 3 * SLOT, wl + 3 * SLOT, ab1, BA, 64,  1, 0, nullptr, h1, l1);
    hgemm_kernel<<<gga, 256, 2 * STAGE_SZ>>>(h1, l1, 256, wh + 4 * SLOT, wl + 4 * SLOT, ab2, BA, 256, 1, 0, nullptr, h2, l2);
    hgemm_kernel<<<gga, 256, 2 * STAGE_SZ>>>(h2, l2, 256, wh + 5 * SLOT, wl + 5 * SLOT, ab3, BA, 256, 0, 2, nullptr, actvh, nullptr);

    // counting sort of edges by src
    zero_cnt_kernel<<<(A + 1 + 255) / 256, 256>>>(A);
    hist_kernel<<<(E + 255) / 256, 256>>>(src, E);
    scan_kernel<<<1, 256>>>(A);
    scatter_kernel<<<(E + 255) / 256, 256>>>(src, E);

    // gather with in-loop dist lookup
    float* out_a = (float*)d_out;
    float* out_v = (float*)d_out + (size_t)BA * NFEAT;
    gather_kernel<<<A, 256>>>((const float4*)table, (const uint2*)actvh,
                              x_v, r_ij, dst, out_a, out_v, A);
}

// round 5
// speedup vs baseline: 5.0480x; 1.1426x over previous
#include <cuda_runtime.h>
#include <cuda_fp16.h>
#include <cstdint>

#define NFEAT 64
#define NHID  256
#define EMAX  320000
#define AMAX  10000
#define BAMAX 40000
#define EPS_F 0.1f
#define COEF0 0.31415926535897931f   // pi / R0, R0 = 10
#define NTAB  16384
#define DMAX  10.0f
#define TSCALE ((float)NTAB / DMAX)
#define SLOT  (256 * 256)

// ---------------- scratch (device globals; no allocation allowed) ------------
__device__ __half g_te_h[(size_t)NTAB * 64];
__device__ __half g_te_l[(size_t)NTAB * 64];
__device__ __half g_xa_h[(size_t)BAMAX * 64];
__device__ __half g_xa_l[(size_t)BAMAX * 64];
__device__ __half g_t1h[(size_t)NTAB * NHID];
__device__ __half g_t1l[(size_t)NTAB * NHID];
__device__ __half g_t2h[(size_t)NTAB * NHID];
__device__ __half g_t2l[(size_t)NTAB * NHID];
__device__ __half g_a1h[(size_t)BAMAX * NHID];
__device__ __half g_a1l[(size_t)BAMAX * NHID];
__device__ __half g_a2h[(size_t)BAMAX * NHID];
__device__ __half g_a2l[(size_t)BAMAX * NHID];
__device__ float  g_table[(size_t)NTAB * NHID];   // dist MLP lookup, [k][feat][4]
__device__ __half g_actvh[(size_t)BAMAX * NHID];  // actv MLP out, [row][feat][4]
__device__ __half g_wh[6 * SLOT];
__device__ __half g_wl[6 * SLOT];
__device__ int g_cnt[AMAX + 1];
__device__ int g_off[AMAX + 1];
__device__ int g_pos[AMAX];
__device__ int g_elist[EMAX];

// ---------------- PTX helpers -------------------------------------------------
__device__ __forceinline__ uint32_t smem_u32(const void* p) {
    uint32_t a;
    asm("{ .reg .u64 t; cvta.to.shared.u64 t, %1; cvt.u32.u64 %0, t; }" : "=r"(a) : "l"(p));
    return a;
}
#define CP16(saddr, gptr) \
    asm volatile("cp.async.cg.shared.global [%0], [%1], 16;" :: "r"(saddr), "l"(gptr) : "memory")
#define CP_COMMIT asm volatile("cp.async.commit_group;" ::: "memory")
#define CP_WAIT0 asm volatile("cp.async.wait_group 0;" ::: "memory")
#define CP_WAIT1 asm volatile("cp.async.wait_group 1;" ::: "memory")

__device__ __forceinline__ void ldsm_x4(uint32_t* r, uint32_t addr) {
    asm volatile("ldmatrix.sync.aligned.m8n8.x4.shared.b16 {%0,%1,%2,%3}, [%4];"
                 : "=r"(r[0]), "=r"(r[1]), "=r"(r[2]), "=r"(r[3]) : "r"(addr));
}
__device__ __forceinline__ void mma16816(float* c, const uint32_t* a, uint32_t b0, uint32_t b1) {
    asm volatile("mma.sync.aligned.m16n8k16.row.col.f32.f16.f16.f32 "
                 "{%0,%1,%2,%3}, {%4,%5,%6,%7}, {%8,%9}, {%0,%1,%2,%3};"
                 : "+f"(c[0]), "+f"(c[1]), "+f"(c[2]), "+f"(c[3])
                 : "r"(a[0]), "r"(a[1]), "r"(a[2]), "r"(a[3]), "r"(b0), "r"(b1));
}
__device__ __forceinline__ void split_h(float v, __half& h, __half& l) {
    h = __float2half_rn(v);
    l = __float2half_rn(v - __half2float(h));
}

// ---------------- prep kernel: tencode + split(x_a) + 6x wtrans + zero_cnt ----
__global__ void prep_kernel(
    const float* __restrict__ x_a,
    const float* __restrict__ dW1, const float* __restrict__ dW2, const float* __restrict__ dW3,
    const float* __restrict__ aW1, const float* __restrict__ aW2, const float* __restrict__ aW3,
    int BA, int A)
{
    const int tid = threadIdx.x;
    int bid = blockIdx.x;
    const int S0 = NTAB * 64 / 256;        // 4096 tencode blocks
    const int S1 = (BA * 64) / 256;        // split blocks (BA mult of 4)

    if (bid < S0) {
        int t = bid * 256 + tid;
        int k = t >> 6, j = t & 63;
        float d = (float)k * (DMAX / (float)NTAB);
        int kk = j & 31;
        float ph = (float)(1 + (kk >> 1)) * COEF0 * d;
        float v = (j < 32) ? cosf(ph) : sinf(ph);
        __half h, l;
        split_h(v, h, l);
        g_te_h[t] = h; g_te_l[t] = l;
        return;
    }
    bid -= S0;
    if (bid < S1) {
        int t = bid * 256 + tid;
        __half h, l;
        split_h(x_a[t], h, l);
        g_xa_h[t] = h; g_xa_l[t] = l;
        return;
    }
    bid -= S1;
    if (bid < 1152) {
        const float* W; int K, slot;
        if      (bid < 64)  { W = dW1; K = 64;  slot = 0; }
        else if (bid < 320) { W = dW2; K = 256; slot = 1; bid -= 64; }
        else if (bid < 576) { W = dW3; K = 256; slot = 2; bid -= 320; }
        else if (bid < 640) { W = aW1; K = 64;  slot = 3; bid -= 576; }
        else if (bid < 896) { W = aW2; K = 256; slot = 4; bid -= 640; }
        else                { W = aW3; K = 256; slot = 5; bid -= 896; }
        int t = bid * 256 + tid;
        int n = t & 255, k = t >> 8;
        __half h, l;
        split_h(W[(size_t)k * 256 + n], h, l);
        g_wh[(size_t)slot * SLOT + (size_t)n * K + k] = h;
        g_wl[(size_t)slot * SLOT + (size_t)n * K + k] = l;
        return;
    }
    bid -= 1152;
    int t = bid * 256 + tid;
    if (t <= A) g_cnt[t] = 0;
}

// ---------------- GEMM problem descriptor + body ------------------------------
struct GP {
    const __half* Ahi; const __half* Alo; int lda;
    const __half* Bhi; const __half* Blo;
    const float* bias;
    int M, K, act, mode;       // mode 0: fp16 hi/lo out; 1: fp32 perm; 2: fp16 perm
    float* OutF; __half* OHi; __half* OLo;
};

#define HBK 64
#define A_HI_OFF 0
#define A_LO_OFF 18432
#define B_HI_OFF 36864
#define B_LO_OFF 55296
#define STAGE_SZ 73728
#define ROWB 144   // 72 halves per row

__device__ __forceinline__ void gemm_body(const GP p, int bx, int by) {
    extern __shared__ char smem[];
    const uint32_t sbase = smem_u32(smem);
    const int tid = threadIdx.x;
    const int lane = tid & 31;
    const int wid = tid >> 5;
    const int warp_m = wid & 3;
    const int warp_n = wid >> 2;
    const int row0 = bx * 128;
    const int col0 = by * 128;

    const uint32_t aoff = (uint32_t)(warp_m * 32 + (lane & 15)) * ROWB + ((lane >> 4) << 4);
    const uint32_t boff = (uint32_t)(warp_n * 64 + (lane & 7) + ((lane >> 4) << 3)) * ROWB
                        + (((lane >> 3) & 1) << 4);

    float acc[2][8][4];
#pragma unroll
    for (int tm = 0; tm < 2; tm++)
#pragma unroll
        for (int tn = 0; tn < 8; tn++)
#pragma unroll
            for (int j = 0; j < 4; j++) acc[tm][tn][j] = 0.f;

    const int NC = p.K / HBK;
    const int M = p.M;
    const int lda = p.lda;
    const int K = p.K;

    auto load_stage = [&](int buf, int kb) {
        const uint32_t sb = sbase + buf * STAGE_SZ;
#pragma unroll
        for (int it = 0; it < 4; it++) {
            int idx = tid + it * 256;
            int r = idx >> 3, cs = idx & 7;
            uint32_t so = (uint32_t)r * ROWB + cs * 16;
            size_t ga = (size_t)min(row0 + r, M - 1) * lda + kb + cs * 8;
            CP16(sb + A_HI_OFF + so, p.Ahi + ga);
            CP16(sb + A_LO_OFF + so, p.Alo + ga);
            size_t gb = (size_t)(col0 + r) * K + kb + cs * 8;
            CP16(sb + B_HI_OFF + so, p.Bhi + gb);
            CP16(sb + B_LO_OFF + so, p.Blo + gb);
        }
    };

    load_stage(0, 0);
    CP_COMMIT;
    if (NC > 1) { load_stage(1, HBK); CP_COMMIT; }

    for (int c = 0; c < NC; c++) {
        if (c + 1 < NC) { CP_WAIT1; } else { CP_WAIT0; }
        __syncthreads();
        const uint32_t sb = sbase + (c & 1) * STAGE_SZ;
        const uint32_t abase = sb + aoff;
        const uint32_t bbase = sb + B_HI_OFF + boff;
#pragma unroll
        for (int ks = 0; ks < 4; ks++) {
            uint32_t ah[2][4], al[2][4], bb[4][4];
            ldsm_x4(ah[0], abase + ks * 32);
            ldsm_x4(ah[1], abase + 16 * ROWB + ks * 32);
            ldsm_x4(al[0], abase + A_LO_OFF + ks * 32);
            ldsm_x4(al[1], abase + A_LO_OFF + 16 * ROWB + ks * 32);
#pragma unroll
            for (int tg = 0; tg < 4; tg++)
                ldsm_x4(bb[tg], bbase + tg * 16 * ROWB + ks * 32);
#pragma unroll
            for (int tm = 0; tm < 2; tm++)
#pragma unroll
                for (int tn = 0; tn < 8; tn++) {
                    uint32_t b0 = bb[tn >> 1][(tn & 1) * 2];
                    uint32_t b1 = bb[tn >> 1][(tn & 1) * 2 + 1];
                    mma16816(acc[tm][tn], ah[tm], b0, b1);
                    mma16816(acc[tm][tn], al[tm], b0, b1);
                }
#pragma unroll
            for (int tg = 0; tg < 4; tg++)
                ldsm_x4(bb[tg], bbase + (B_LO_OFF - B_HI_OFF) + tg * 16 * ROWB + ks * 32);
#pragma unroll
            for (int tm = 0; tm < 2; tm++)
#pragma unroll
                for (int tn = 0; tn < 8; tn++) {
                    uint32_t b0 = bb[tn >> 1][(tn & 1) * 2];
                    uint32_t b1 = bb[tn >> 1][(tn & 1) * 2 + 1];
                    mma16816(acc[tm][tn], ah[tm], b0, b1);
                }
        }
        if (c + 2 < NC) {
            __syncthreads();
            load_stage(c & 1, (c + 2) * HBK);
            CP_COMMIT;
        }
    }

#pragma unroll
    for (int tm = 0; tm < 2; tm++)
#pragma unroll
        for (int tn = 0; tn < 8; tn++) {
            int r0 = row0 + warp_m * 32 + tm * 16 + (lane >> 2);
            int col = col0 + warp_n * 64 + tn * 8 + 2 * (lane & 3);
            float b0 = __ldg(&p.bias[col]);
            float b1 = __ldg(&p.bias[col + 1]);
            float v0 = acc[tm][tn][0] + b0;
            float v1 = acc[tm][tn][1] + b1;
            float v2 = acc[tm][tn][2] + b0;
            float v3 = acc[tm][tn][3] + b1;
            if (p.act) {
                v0 = v0 / (1.f + __expf(-v0));
                v1 = v1 / (1.f + __expf(-v1));
                v2 = v2 / (1.f + __expf(-v2));
                v3 = v3 / (1.f + __expf(-v3));
            }
            if (p.mode == 0) {
                __half h0, l0, h1, l1;
                if (r0 < M) {
                    split_h(v0, h0, l0); split_h(v1, h1, l1);
                    *(__half2*)&p.OHi[(size_t)r0 * 256 + col] = __halves2half2(h0, h1);
                    *(__half2*)&p.OLo[(size_t)r0 * 256 + col] = __halves2half2(l0, l1);
                }
                if (r0 + 8 < M) {
                    split_h(v2, h0, l0); split_h(v3, h1, l1);
                    *(__half2*)&p.OHi[(size_t)(r0 + 8) * 256 + col] = __halves2half2(h0, h1);
                    *(__half2*)&p.OLo[(size_t)(r0 + 8) * 256 + col] = __halves2half2(l0, l1);
                }
            } else {
                int pc0 = ((col & 63) << 2) | (col >> 6);
                int pc1 = (((col + 1) & 63) << 2) | ((col + 1) >> 6);
                if (p.mode == 1) {
                    if (r0 < M) {
                        p.OutF[(size_t)r0 * 256 + pc0] = v0;
                        p.OutF[(size_t)r0 * 256 + pc1] = v1;
                    }
                    if (r0 + 8 < M) {
                        p.OutF[(size_t)(r0 + 8) * 256 + pc0] = v2;
                        p.OutF[(size_t)(r0 + 8) * 256 + pc1] = v3;
                    }
                } else {
                    if (r0 < M) {
                        p.OHi[(size_t)r0 * 256 + pc0] = __float2half_rn(v0);
                        p.OHi[(size_t)r0 * 256 + pc1] = __float2half_rn(v1);
                    }
                    if (r0 + 8 < M) {
                        p.OHi[(size_t)(r0 + 8) * 256 + pc0] = __float2half_rn(v2);
                        p.OHi[(size_t)(r0 + 8) * 256 + pc1] = __float2half_rn(v3);
                    }
                }
            }
        }
}

// ---------------- single-block exclusive scan (device body) -------------------
__device__ void scan_body(int A) {
    __shared__ int sh[256];
    int tid = threadIdx.x;
    int chunk = (A + 255) >> 8;
    int base = tid * chunk;
    int sum = 0;
    for (int j = 0; j < chunk; j++) {
        int idx = base + j;
        if (idx < A) sum += g_cnt[idx];
    }
    sh[tid] = sum;
    __syncthreads();
    for (int off = 1; off < 256; off <<= 1) {
        int v = 0;
        if (tid >= off) v = sh[tid - off];
        __syncthreads();
        sh[tid] += v;
        __syncthreads();
    }
    int run = (tid == 0) ? 0 : sh[tid - 1];
    for (int j = 0; j < chunk; j++) {
        int idx = base + j;
        if (idx < A) {
            g_off[idx] = run;
            g_pos[idx] = run;
            run += g_cnt[idx];
        }
    }
    if (base < A && A <= base + chunk) g_off[A] = run;
}

// ---------------- merged layer kernel: 2 GEMM problems + sort-step aux CTAs ---
// aux: 1 = hist (128 CTAs), 2 = scan (1 CTA), 3 = scatter (128 CTAs)
__global__ __launch_bounds__(256) void layer_kernel(
    GP pa, GP pt, int nA2, int nT2,
    int aux, const int* __restrict__ src, int E, int A)
{
    int bid = blockIdx.x;
    const int nG = nA2 + nT2;
    if (bid < nG) {
        bool isA = bid < nA2;
        GP p = isA ? pa : pt;
        int lb = isA ? bid : bid - nA2;
        gemm_body(p, lb >> 1, lb & 1);
        return;
    }
    int abid = bid - nG;
    int tid = threadIdx.x;
    if (aux == 1) {
        for (int t = abid * 256 + tid; t < E; t += 128 * 256)
            atomicAdd(&g_cnt[src[t]], 1);
    } else if (aux == 2) {
        scan_body(A);
    } else if (aux == 3) {
        for (int t = abid * 256 + tid; t < E; t += 128 * 256) {
            int pp = atomicAdd(&g_pos[src[t]], 1);
            g_elist[pp] = t;
        }
    }
}

// ---------------- per-atom gather with in-loop table lerp --------------------
__global__ __launch_bounds__(256) void gather_kernel(
    const float4* __restrict__ T4,
    const uint2* __restrict__ P4,
    const float* __restrict__ x_v, const float* __restrict__ r_ij,
    const int* __restrict__ dst,
    float* __restrict__ out_a, float* __restrict__ out_v, int A)
{
    int a = blockIdx.x;
    int f = threadIdx.x & 63;
    int b = threadIdx.x >> 6;
    int p0 = g_off[a];
    int p1 = g_off[a + 1];

    float av0 = 0.f, av1 = 0.f, av2 = 0.f, aa = 0.f;
    for (int p = p0; p < p1; ++p) {
        int e = g_elist[p];
        float rx = __ldg(&r_ij[e * 3 + 0]);
        float ry = __ldg(&r_ij[e * 3 + 1]);
        float rz = __ldg(&r_ij[e * 3 + 2]);
        float d2s = rx * rx + ry * ry + rz * rz;
        float d = sqrtf(d2s);
        float inv = rsqrtf(EPS_F + d2s);
        float d0 = rx * inv, d1 = ry * inv, d2 = rz * inv;

        float idxf = d * TSCALE;
        int k = (int)idxf;
        if (k > NTAB - 2) k = NTAB - 2;
        float w = idxf - (float)k;
        if (w > 1.f) w = 1.f;

        float4 t0 = __ldg(&T4[(size_t)k * 64 + f]);
        float4 t1 = __ldg(&T4[(size_t)(k + 1) * 64 + f]);
        float q0 = fmaf(w, t1.x - t0.x, t0.x);
        float q1 = fmaf(w, t1.y - t0.y, t0.y);
        float q2 = fmaf(w, t1.z - t0.z, t0.z);
        float q3 = fmaf(w, t1.w - t0.w, t0.w);

        int dd = __ldg(&dst[e]);
        uint2 pr = __ldg(&P4[(size_t)(b * A + dd) * 64 + f]);
        __half2 pa = *(__half2*)&pr.x;
        __half2 pb = *(__half2*)&pr.y;
        q0 *= __low2float(pa);
        q1 *= __high2float(pa);
        q2 *= __low2float(pb);
        q3 *= __high2float(pb);

        const float* V = x_v + (size_t)((b * A + dd) * 64 + f) * 3;
        float v0 = __ldg(&V[0]), v1 = __ldg(&V[1]), v2 = __ldg(&V[2]);
        float c0 = v1 * d2 - v2 * d1;
        float c1 = v2 * d0 - v0 * d2;
        float c2 = v0 * d1 - v1 * d0;
        av0 += v0 * q0 + c0 * q1 + d0 * q2;
        av1 += v1 * q0 + c1 * q1 + d1 * q2;
        av2 += v2 * q0 + c2 * q1 + d2 * q2;
        aa  += q3;
    }
    out_a[(size_t)(b * A + a) * 64 + f] = aa;
    float* OV = out_v + (size_t)((b * A + a) * 64 + f) * 3;
    OV[0] = av0;
    OV[1] = av1;
    OV[2] = av2;
}

// ---------------- launch ------------------------------------------------------
extern "C" void kernel_launch(void* const* d_in, const int* in_sizes, int n_in,
                              void* d_out, int out_size) {
    const float* x_a  = (const float*)d_in[0];
    const float* x_v  = (const float*)d_in[1];
    const float* r_ij = (const float*)d_in[2];
    const int*   src  = (const int*)d_in[3];
    const int*   dst  = (const int*)d_in[4];
    const float* dW1 = (const float*)d_in[5];
    const float* db1 = (const float*)d_in[6];
    const float* dW2 = (const float*)d_in[7];
    const float* db2 = (const float*)d_in[8];
    const float* dW3 = (const float*)d_in[9];
    const float* db3 = (const float*)d_in[10];
    const float* aW1 = (const float*)d_in[11];
    const float* ab1 = (const float*)d_in[12];
    const float* aW2 = (const float*)d_in[13];
    const float* ab2 = (const float*)d_in[14];
    const float* aW3 = (const float*)d_in[15];
    const float* ab3 = (const float*)d_in[16];

    const int E  = in_sizes[3];
    const int BA = in_sizes[0] / NFEAT;
    const int A  = BA / 4;                 // B = 4

    __half *te_h, *te_l, *xa_h, *xa_l;
    __half *t1h, *t1l, *t2h, *t2l, *a1h, *a1l, *a2h, *a2l;
    __half *wh, *wl, *actvh;
    float *table;
    cudaGetSymbolAddress((void**)&te_h, g_te_h);
    cudaGetSymbolAddress((void**)&te_l, g_te_l);
    cudaGetSymbolAddress((void**)&xa_h, g_xa_h);
    cudaGetSymbolAddress((void**)&xa_l, g_xa_l);
    cudaGetSymbolAddress((void**)&t1h, g_t1h);
    cudaGetSymbolAddress((void**)&t1l, g_t1l);
    cudaGetSymbolAddress((void**)&t2h, g_t2h);
    cudaGetSymbolAddress((void**)&t2l, g_t2l);
    cudaGetSymbolAddress((void**)&a1h, g_a1h);
    cudaGetSymbolAddress((void**)&a1l, g_a1l);
    cudaGetSymbolAddress((void**)&a2h, g_a2h);
    cudaGetSymbolAddress((void**)&a2l, g_a2l);
    cudaGetSymbolAddress((void**)&wh, g_wh);
    cudaGetSymbolAddress((void**)&wl, g_wl);
    cudaGetSymbolAddress((void**)&table, g_table);
    cudaGetSymbolAddress((void**)&actvh, g_actvh);

    cudaFuncSetAttribute(layer_kernel, cudaFuncAttributeMaxDynamicSharedMemorySize, 2 * STAGE_SZ);

    // 1) prep: tencode + split(x_a) + wtrans x6 + zero_cnt in one launch
    const int prep_blocks = (NTAB * 64 / 256) + (BA * 64) / 256 + 1152 + (A + 1 + 255) / 256;
    prep_kernel<<<prep_blocks, 256>>>(x_a, dW1, dW2, dW3, aW1, aW2, aW3, BA, A);

    const int nA2 = 2 * ((BA + 127) / 128);
    const int nT2 = 2 * (NTAB / 128);

    // 2) layer 1 (K=64) + hist
    {
        GP pa = { xa_h, xa_l, 64, wh + 3 * SLOT, wl + 3 * SLOT, ab1, BA, 64, 1, 0, nullptr, a1h, a1l };
        GP pt = { te_h, te_l, 64, wh + 0 * SLOT, wl + 0 * SLOT, db1, NTAB, 64, 1, 0, nullptr, t1h, t1l };
        layer_kernel<<<nA2 + nT2 + 128, 256, 2 * STAGE_SZ>>>(pa, pt, nA2, nT2, 1, src, E, A);
    }
    // 3) layer 2 (K=256) + scan
    {
        GP pa = { a1h, a1l, 256, wh + 4 * SLOT, wl + 4 * SLOT, ab2, BA, 256, 1, 0, nullptr, a2h, a2l };
        GP pt = { t1h, t1l, 256, wh + 1 * SLOT, wl + 1 * SLOT, db2, NTAB, 256, 1, 0, nullptr, t2h, t2l };
        layer_kernel<<<nA2 + nT2 + 1, 256, 2 * STAGE_SZ>>>(pa, pt, nA2, nT2, 2, src, E, A);
    }
    // 4) layer 3 (K=256, no act) + scatter; outputs permuted table (fp32) / actv (fp16)
    {
        GP pa = { a2h, a2l, 256, wh + 5 * SLOT, wl + 5 * SLOT, ab3, BA, 256, 0, 2, nullptr, actvh, nullptr };
        GP pt = { t2h, t2l, 256, wh + 2 * SLOT, wl + 2 * SLOT, db3, NTAB, 256, 0, 1, table, nullptr, nullptr };
        layer_kernel<<<nA2 + nT2 + 128, 256, 2 * STAGE_SZ>>>(pa, pt, nA2, nT2, 3, src, E, A);
    }

    // 5) gather with in-loop dist lookup
    float* out_a = (float*)d_out;
    float* out_v = (float*)d_out + (size_t)BA * NFEAT;
    gather_kernel<<<A, 256>>>((const float4*)table, (const uint2*)actvh,
                              x_v, r_ij, dst, out_a, out_v, A);
}

// round 6
// speedup vs baseline: 5.5783x; 1.1051x over previous
#include <cuda_runtime.h>
#include <cuda_fp16.h>
#include <cstdint>

#define NFEAT 64
#define NHID  256
#define EMAX  320000
#define AMAX  10000
#define BAMAX 40000
#define EPS_F 0.1f
#define COEF0 0.31415926535897931f   // pi / R0, R0 = 10
#define NTAB  16384
#define DMAX  10.0f
#define TSCALE ((float)NTAB / DMAX)
#define SLOT  (256 * 256)

// ---------------- scratch (device globals; no allocation allowed) ------------
__device__ __half g_te_h[(size_t)NTAB * 64];
__device__ __half g_te_l[(size_t)NTAB * 64];
__device__ __half g_xa_h[(size_t)BAMAX * 64];
__device__ __half g_xa_l[(size_t)BAMAX * 64];
__device__ __half g_t1h[(size_t)NTAB * NHID];
__device__ __half g_t1l[(size_t)NTAB * NHID];
__device__ __half g_t2h[(size_t)NTAB * NHID];
__device__ __half g_t2l[(size_t)NTAB * NHID];
__device__ __half g_a1h[(size_t)BAMAX * NHID];
__device__ __half g_a1l[(size_t)BAMAX * NHID];
__device__ __half g_a2h[(size_t)BAMAX * NHID];
__device__ __half g_a2l[(size_t)BAMAX * NHID];
__device__ __half g_tableh[(size_t)NTAB * NHID];  // dist MLP lookup fp16, [k][feat][4]
__device__ __half g_actvh[(size_t)BAMAX * NHID];  // actv MLP out fp16, [row][feat][4]
__device__ __half g_xvh[(size_t)BAMAX * 64 * 4];  // x_v packed half4 (v0,v1,v2,0)
__device__ __half g_wh[6 * SLOT];
__device__ __half g_wl[6 * SLOT];
__device__ int g_cnt[AMAX + 1];
__device__ int g_off[AMAX + 1];
__device__ int g_pos[AMAX];
__device__ int g_elist[EMAX];

// ---------------- PTX helpers -------------------------------------------------
__device__ __forceinline__ uint32_t smem_u32(const void* p) {
    uint32_t a;
    asm("{ .reg .u64 t; cvta.to.shared.u64 t, %1; cvt.u32.u64 %0, t; }" : "=r"(a) : "l"(p));
    return a;
}
#define CP16(saddr, gptr) \
    asm volatile("cp.async.cg.shared.global [%0], [%1], 16;" :: "r"(saddr), "l"(gptr) : "memory")
#define CP_COMMIT asm volatile("cp.async.commit_group;" ::: "memory")
#define CP_WAIT0 asm volatile("cp.async.wait_group 0;" ::: "memory")
#define CP_WAIT1 asm volatile("cp.async.wait_group 1;" ::: "memory")

__device__ __forceinline__ void ldsm_x4(uint32_t* r, uint32_t addr) {
    asm volatile("ldmatrix.sync.aligned.m8n8.x4.shared.b16 {%0,%1,%2,%3}, [%4];"
                 : "=r"(r[0]), "=r"(r[1]), "=r"(r[2]), "=r"(r[3]) : "r"(addr));
}
__device__ __forceinline__ void mma16816(float* c, const uint32_t* a, uint32_t b0, uint32_t b1) {
    asm volatile("mma.sync.aligned.m16n8k16.row.col.f32.f16.f16.f32 "
                 "{%0,%1,%2,%3}, {%4,%5,%6,%7}, {%8,%9}, {%0,%1,%2,%3};"
                 : "+f"(c[0]), "+f"(c[1]), "+f"(c[2]), "+f"(c[3])
                 : "r"(a[0]), "r"(a[1]), "r"(a[2]), "r"(a[3]), "r"(b0), "r"(b1));
}
__device__ __forceinline__ void split_h(float v, __half& h, __half& l) {
    h = __float2half_rn(v);
    l = __float2half_rn(v - __half2float(h));
}

// ---------------- prep: tencode + split(x_a) + wtrans x6 + xv pack + zero ----
__global__ void prep_kernel(
    const float* __restrict__ x_a, const float* __restrict__ x_v,
    const float* __restrict__ dW1, const float* __restrict__ dW2, const float* __restrict__ dW3,
    const float* __restrict__ aW1, const float* __restrict__ aW2, const float* __restrict__ aW3,
    int BA, int A)
{
    const int tid = threadIdx.x;
    int bid = blockIdx.x;
    const int S0 = NTAB * 64 / 256;
    const int S1 = (BA * 64) / 256;

    if (bid < S0) {
        int t = bid * 256 + tid;
        int k = t >> 6, j = t & 63;
        float d = (float)k * (DMAX / (float)NTAB);
        int kk = j & 31;
        float ph = (float)(1 + (kk >> 1)) * COEF0 * d;
        float v = (j < 32) ? cosf(ph) : sinf(ph);
        __half h, l;
        split_h(v, h, l);
        g_te_h[t] = h; g_te_l[t] = l;
        return;
    }
    bid -= S0;
    if (bid < S1) {
        int t = bid * 256 + tid;
        __half h, l;
        split_h(x_a[t], h, l);
        g_xa_h[t] = h; g_xa_l[t] = l;
        return;
    }
    bid -= S1;
    if (bid < S1) {   // x_v pack: [row][3] fp32 -> half4
        int t = bid * 256 + tid;
        float v0 = x_v[(size_t)t * 3 + 0];
        float v1 = x_v[(size_t)t * 3 + 1];
        float v2 = x_v[(size_t)t * 3 + 2];
        __half2* dst = (__half2*)&g_xvh[(size_t)t * 4];
        dst[0] = __floats2half2_rn(v0, v1);
        dst[1] = __floats2half2_rn(v2, 0.f);
        return;
    }
    bid -= S1;
    if (bid < 1152) {
        const float* W; int K, slot;
        if      (bid < 64)  { W = dW1; K = 64;  slot = 0; }
        else if (bid < 320) { W = dW2; K = 256; slot = 1; bid -= 64; }
        else if (bid < 576) { W = dW3; K = 256; slot = 2; bid -= 320; }
        else if (bid < 640) { W = aW1; K = 64;  slot = 3; bid -= 576; }
        else if (bid < 896) { W = aW2; K = 256; slot = 4; bid -= 640; }
        else                { W = aW3; K = 256; slot = 5; bid -= 896; }
        int t = bid * 256 + tid;
        int n = t & 255, k = t >> 8;
        __half h, l;
        split_h(W[(size_t)k * 256 + n], h, l);
        g_wh[(size_t)slot * SLOT + (size_t)n * K + k] = h;
        g_wl[(size_t)slot * SLOT + (size_t)n * K + k] = l;
        return;
    }
    bid -= 1152;
    int t = bid * 256 + tid;
    if (t <= A) g_cnt[t] = 0;
}

// ---------------- GEMM problem descriptor + body ------------------------------
struct GP {
    const __half* Ahi; const __half* Alo; int lda;
    const __half* Bhi; const __half* Blo;
    const float* bias;
    int M, K, act, mode;       // mode 0: fp16 hi/lo out; 2: fp16 permuted out
    __half* OHi; __half* OLo;
};

#define HBK 32
#define ROWB 80    // 32 halves (64B) + 16B pad, 16B-aligned rows
#define TILE_SZ 10240          // 128 rows * 80B
#define A_HI_OFF 0
#define A_LO_OFF 10240
#define B_HI_OFF 20480
#define B_LO_OFF 30720
#define STAGE_SZ 40960

__device__ __forceinline__ void gemm_body(const GP p, int bx, int by) {
    extern __shared__ char smem[];
    const uint32_t sbase = smem_u32(smem);
    const int tid = threadIdx.x;
    const int lane = tid & 31;
    const int wid = tid >> 5;
    const int warp_m = wid & 3;
    const int warp_n = wid >> 2;
    const int row0 = bx * 128;
    const int col0 = by * 128;

    const uint32_t aoff = (uint32_t)(warp_m * 32 + (lane & 15)) * ROWB + ((lane >> 4) << 4);
    const uint32_t boff = (uint32_t)(warp_n * 64 + (lane & 7) + ((lane >> 4) << 3)) * ROWB
                        + (((lane >> 3) & 1) << 4);

    float acc[2][8][4];
#pragma unroll
    for (int tm = 0; tm < 2; tm++)
#pragma unroll
        for (int tn = 0; tn < 8; tn++)
#pragma unroll
            for (int j = 0; j < 4; j++) acc[tm][tn][j] = 0.f;

    const int NC = p.K / HBK;
    const int M = p.M;
    const int lda = p.lda;
    const int K = p.K;

    auto load_stage = [&](int buf, int kb) {
        const uint32_t sb = sbase + buf * STAGE_SZ;
#pragma unroll
        for (int it = 0; it < 2; it++) {
            int idx = tid + it * 256;
            int r = idx >> 2, cs = idx & 3;
            uint32_t so = (uint32_t)r * ROWB + cs * 16;
            size_t ga = (size_t)min(row0 + r, M - 1) * lda + kb + cs * 8;
            CP16(sb + A_HI_OFF + so, p.Ahi + ga);
            CP16(sb + A_LO_OFF + so, p.Alo + ga);
            size_t gb = (size_t)(col0 + r) * K + kb + cs * 8;
            CP16(sb + B_HI_OFF + so, p.Bhi + gb);
            CP16(sb + B_LO_OFF + so, p.Blo + gb);
        }
    };

    load_stage(0, 0);
    CP_COMMIT;
    if (NC > 1) { load_stage(1, HBK); CP_COMMIT; }

    for (int c = 0; c < NC; c++) {
        if (c + 1 < NC) { CP_WAIT1; } else { CP_WAIT0; }
        __syncthreads();
        const uint32_t sb = sbase + (c & 1) * STAGE_SZ;
        const uint32_t abase = sb + aoff;
        const uint32_t bbase = sb + B_HI_OFF + boff;
#pragma unroll
        for (int ks = 0; ks < 2; ks++) {
            uint32_t ah[2][4], al[2][4], bb[4][4];
            ldsm_x4(ah[0], abase + ks * 32);
            ldsm_x4(ah[1], abase + 16 * ROWB + ks * 32);
            ldsm_x4(al[0], abase + A_LO_OFF + ks * 32);
            ldsm_x4(al[1], abase + A_LO_OFF + 16 * ROWB + ks * 32);
#pragma unroll
            for (int tg = 0; tg < 4; tg++)
                ldsm_x4(bb[tg], bbase + tg * 16 * ROWB + ks * 32);
#pragma unroll
            for (int tm = 0; tm < 2; tm++)
#pragma unroll
                for (int tn = 0; tn < 8; tn++) {
                    uint32_t b0 = bb[tn >> 1][(tn & 1) * 2];
                    uint32_t b1 = bb[tn >> 1][(tn & 1) * 2 + 1];
                    mma16816(acc[tm][tn], ah[tm], b0, b1);
                    mma16816(acc[tm][tn], al[tm], b0, b1);
                }
#pragma unroll
            for (int tg = 0; tg < 4; tg++)
                ldsm_x4(bb[tg], bbase + (B_LO_OFF - B_HI_OFF) + tg * 16 * ROWB + ks * 32);
#pragma unroll
            for (int tm = 0; tm < 2; tm++)
#pragma unroll
                for (int tn = 0; tn < 8; tn++) {
                    uint32_t b0 = bb[tn >> 1][(tn & 1) * 2];
                    uint32_t b1 = bb[tn >> 1][(tn & 1) * 2 + 1];
                    mma16816(acc[tm][tn], ah[tm], b0, b1);
                }
        }
        if (c + 2 < NC) {
            __syncthreads();
            load_stage(c & 1, (c + 2) * HBK);
            CP_COMMIT;
        }
    }

#pragma unroll
    for (int tm = 0; tm < 2; tm++)
#pragma unroll
        for (int tn = 0; tn < 8; tn++) {
            int r0 = row0 + warp_m * 32 + tm * 16 + (lane >> 2);
            int col = col0 + warp_n * 64 + tn * 8 + 2 * (lane & 3);
            float b0 = __ldg(&p.bias[col]);
            float b1 = __ldg(&p.bias[col + 1]);
            float v0 = acc[tm][tn][0] + b0;
            float v1 = acc[tm][tn][1] + b1;
            float v2 = acc[tm][tn][2] + b0;
            float v3 = acc[tm][tn][3] + b1;
            if (p.act) {
                v0 = v0 / (1.f + __expf(-v0));
                v1 = v1 / (1.f + __expf(-v1));
                v2 = v2 / (1.f + __expf(-v2));
                v3 = v3 / (1.f + __expf(-v3));
            }
            if (p.mode == 0) {
                __half h0, l0, h1, l1;
                if (r0 < M) {
                    split_h(v0, h0, l0); split_h(v1, h1, l1);
                    *(__half2*)&p.OHi[(size_t)r0 * 256 + col] = __halves2half2(h0, h1);
                    *(__half2*)&p.OLo[(size_t)r0 * 256 + col] = __halves2half2(l0, l1);
                }
                if (r0 + 8 < M) {
                    split_h(v2, h0, l0); split_h(v3, h1, l1);
                    *(__half2*)&p.OHi[(size_t)(r0 + 8) * 256 + col] = __halves2half2(h0, h1);
                    *(__half2*)&p.OLo[(size_t)(r0 + 8) * 256 + col] = __halves2half2(l0, l1);
                }
            } else {
                int pc0 = ((col & 63) << 2) | (col >> 6);
                int pc1 = (((col + 1) & 63) << 2) | ((col + 1) >> 6);
                if (r0 < M) {
                    p.OHi[(size_t)r0 * 256 + pc0] = __float2half_rn(v0);
                    p.OHi[(size_t)r0 * 256 + pc1] = __float2half_rn(v1);
                }
                if (r0 + 8 < M) {
                    p.OHi[(size_t)(r0 + 8) * 256 + pc0] = __float2half_rn(v2);
                    p.OHi[(size_t)(r0 + 8) * 256 + pc1] = __float2half_rn(v3);
                }
            }
        }
}

// ---------------- single-block exclusive scan (device body) -------------------
__device__ void scan_body(int A) {
    __shared__ int sh[256];
    int tid = threadIdx.x;
    int chunk = (A + 255) >> 8;
    int base = tid * chunk;
    int sum = 0;
    for (int j = 0; j < chunk; j++) {
        int idx = base + j;
        if (idx < A) sum += g_cnt[idx];
    }
    sh[tid] = sum;
    __syncthreads();
    for (int off = 1; off < 256; off <<= 1) {
        int v = 0;
        if (tid >= off) v = sh[tid - off];
        __syncthreads();
        sh[tid] += v;
        __syncthreads();
    }
    int run = (tid == 0) ? 0 : sh[tid - 1];
    for (int j = 0; j < chunk; j++) {
        int idx = base + j;
        if (idx < A) {
            g_off[idx] = run;
            g_pos[idx] = run;
            run += g_cnt[idx];
        }
    }
    if (base < A && A <= base + chunk) g_off[A] = run;
}

// ---------------- merged layer kernel: 2 GEMM problems + sort-step aux CTAs ---
__global__ void __launch_bounds__(256, 2) layer_kernel(
    GP pa, GP pt, int nA2, int nT2,
    int aux, const int* __restrict__ src, int E, int A)
{
    int bid = blockIdx.x;
    const int nG = nA2 + nT2;
    if (bid < nG) {
        bool isA = bid < nA2;
        GP p = isA ? pa : pt;
        int lb = isA ? bid : bid - nA2;
        gemm_body(p, lb >> 1, lb & 1);
        return;
    }
    int abid = bid - nG;
    int tid = threadIdx.x;
    if (aux == 1) {
        for (int t = abid * 256 + tid; t < E; t += 128 * 256)
            atomicAdd(&g_cnt[src[t]], 1);
    } else if (aux == 2) {
        scan_body(A);
    } else if (aux == 3) {
        for (int t = abid * 256 + tid; t < E; t += 128 * 256) {
            int pp = atomicAdd(&g_pos[src[t]], 1);
            g_elist[pp] = t;
        }
    }
}

// ---------------- per-atom gather: fp16 table lerp + fp16 actv + fp16 x_v -----
__global__ __launch_bounds__(256) void gather_kernel(
    const uint2* __restrict__ T4,           // g_tableh: [k][feat] 4 halves
    const uint2* __restrict__ P4,           // g_actvh: [row][feat] 4 halves
    const uint2* __restrict__ XV,           // g_xvh: [row*64+f] 4 halves
    const float* __restrict__ r_ij,
    const int* __restrict__ dst,
    float* __restrict__ out_a, float* __restrict__ out_v, int A)
{
    int a = blockIdx.x;
    int f = threadIdx.x & 63;
    int b = threadIdx.x >> 6;
    int p0 = g_off[a];
    int p1 = g_off[a + 1];

    float av0 = 0.f, av1 = 0.f, av2 = 0.f, aa = 0.f;
    for (int p = p0; p < p1; ++p) {
        int e = g_elist[p];
        float rx = __ldg(&r_ij[e * 3 + 0]);
        float ry = __ldg(&r_ij[e * 3 + 1]);
        float rz = __ldg(&r_ij[e * 3 + 2]);
        float d2s = rx * rx + ry * ry + rz * rz;
        float d = sqrtf(d2s);
        float inv = rsqrtf(EPS_F + d2s);
        float d0 = rx * inv, d1 = ry * inv, d2 = rz * inv;

        float idxf = d * TSCALE;
        int k = (int)idxf;
        if (k > NTAB - 2) k = NTAB - 2;
        float w = idxf - (float)k;
        if (w > 1.f) w = 1.f;

        uint2 t0u = __ldg(&T4[(size_t)k * 64 + f]);
        uint2 t1u = __ldg(&T4[(size_t)(k + 1) * 64 + f]);
        float2 t0a = __half22float2(*(__half2*)&t0u.x);
        float2 t0b = __half22float2(*(__half2*)&t0u.y);
        float2 t1a = __half22float2(*(__half2*)&t1u.x);
        float2 t1b = __half22float2(*(__half2*)&t1u.y);
        float q0 = fmaf(w, t1a.x - t0a.x, t0a.x);
        float q1 = fmaf(w, t1a.y - t0a.y, t0a.y);
        float q2 = fmaf(w, t1b.x - t0b.x, t0b.x);
        float q3 = fmaf(w, t1b.y - t0b.y, t0b.y);

        int dd = __ldg(&dst[e]);
        size_t ridx = (size_t)(b * A + dd) * 64 + f;
        uint2 pr = __ldg(&P4[ridx]);
        __half2 pra = *(__half2*)&pr.x;
        __half2 prb = *(__half2*)&pr.y;
        q0 *= __low2float(pra);
        q1 *= __high2float(pra);
        q2 *= __low2float(prb);
        q3 *= __high2float(prb);

        uint2 vr = __ldg(&XV[ridx]);
        float2 va = __half22float2(*(__half2*)&vr.x);
        float v2f = __low2float(*(__half2*)&vr.y);
        float v0 = va.x, v1 = va.y, v2 = v2f;
        float c0 = v1 * d2 - v2 * d1;
        float c1 = v2 * d0 - v0 * d2;
        float c2 = v0 * d1 - v1 * d0;
        av0 += v0 * q0 + c0 * q1 + d0 * q2;
        av1 += v1 * q0 + c1 * q1 + d1 * q2;
        av2 += v2 * q0 + c2 * q1 + d2 * q2;
        aa  += q3;
    }
    out_a[(size_t)(b * A + a) * 64 + f] = aa;
    float* OV = out_v + (size_t)((b * A + a) * 64 + f) * 3;
    OV[0] = av0;
    OV[1] = av1;
    OV[2] = av2;
}

// ---------------- launch ------------------------------------------------------
extern "C" void kernel_launch(void* const* d_in, const int* in_sizes, int n_in,
                              void* d_out, int out_size) {
    const float* x_a  = (const float*)d_in[0];
    const float* x_v  = (const float*)d_in[1];
    const float* r_ij = (const float*)d_in[2];
    const int*   src  = (const int*)d_in[3];
    const int*   dst  = (const int*)d_in[4];
    const float* dW1 = (const float*)d_in[5];
    const float* db1 = (const float*)d_in[6];
    const float* dW2 = (const float*)d_in[7];
    const float* db2 = (const float*)d_in[8];
    const float* dW3 = (const float*)d_in[9];
    const float* db3 = (const float*)d_in[10];
    const float* aW1 = (const float*)d_in[11];
    const float* ab1 = (const float*)d_in[12];
    const float* aW2 = (const float*)d_in[13];
    const float* ab2 = (const float*)d_in[14];
    const float* aW3 = (const float*)d_in[15];
    const float* ab3 = (const float*)d_in[16];

    const int E  = in_sizes[3];
    const int BA = in_sizes[0] / NFEAT;
    const int A  = BA / 4;                 // B = 4

    __half *te_h, *te_l, *xa_h, *xa_l;
    __half *t1h, *t1l, *t2h, *t2l, *a1h, *a1l, *a2h, *a2l;
    __half *wh, *wl, *actvh, *tableh, *xvh;
    cudaGetSymbolAddress((void**)&te_h, g_te_h);
    cudaGetSymbolAddress((void**)&te_l, g_te_l);
    cudaGetSymbolAddress((void**)&xa_h, g_xa_h);
    cudaGetSymbolAddress((void**)&xa_l, g_xa_l);
    cudaGetSymbolAddress((void**)&t1h, g_t1h);
    cudaGetSymbolAddress((void**)&t1l, g_t1l);
    cudaGetSymbolAddress((void**)&t2h, g_t2h);
    cudaGetSymbolAddress((void**)&t2l, g_t2l);
    cudaGetSymbolAddress((void**)&a1h, g_a1h);
    cudaGetSymbolAddress((void**)&a1l, g_a1l);
    cudaGetSymbolAddress((void**)&a2h, g_a2h);
    cudaGetSymbolAddress((void**)&a2l, g_a2l);
    cudaGetSymbolAddress((void**)&wh, g_wh);
    cudaGetSymbolAddress((void**)&wl, g_wl);
    cudaGetSymbolAddress((void**)&tableh, g_tableh);
    cudaGetSymbolAddress((void**)&actvh, g_actvh);
    cudaGetSymbolAddress((void**)&xvh, g_xvh);

    cudaFuncSetAttribute(layer_kernel, cudaFuncAttributeMaxDynamicSharedMemorySize, 2 * STAGE_SZ);

    // 1) prep
    const int S1 = (BA * 64) / 256;
    const int prep_blocks = (NTAB * 64 / 256) + 2 * S1 + 1152 + (A + 1 + 255) / 256;
    prep_kernel<<<prep_blocks, 256>>>(x_a, x_v, dW1, dW2, dW3, aW1, aW2, aW3, BA, A);

    const int nA2 = 2 * ((BA + 127) / 128);
    const int nT2 = 2 * (NTAB / 128);

    // 2) layer 1 (K=64) + hist
    {
        GP pa = { xa_h, xa_l, 64, wh + 3 * SLOT, wl + 3 * SLOT, ab1, BA, 64, 1, 0, a1h, a1l };
        GP pt = { te_h, te_l, 64, wh + 0 * SLOT, wl + 0 * SLOT, db1, NTAB, 64, 1, 0, t1h, t1l };
        layer_kernel<<<nA2 + nT2 + 128, 256, 2 * STAGE_SZ>>>(pa, pt, nA2, nT2, 1, src, E, A);
    }
    // 3) layer 2 (K=256) + scan
    {
        GP pa = { a1h, a1l, 256, wh + 4 * SLOT, wl + 4 * SLOT, ab2, BA, 256, 1, 0, a2h, a2l };
        GP pt = { t1h, t1l, 256, wh + 1 * SLOT, wl + 1 * SLOT, db2, NTAB, 256, 1, 0, t2h, t2l };
        layer_kernel<<<nA2 + nT2 + 1, 256, 2 * STAGE_SZ>>>(pa, pt, nA2, nT2, 2, src, E, A);
    }
    // 4) layer 3 (K=256, no act, fp16 permuted outs) + scatter
    {
        GP pa = { a2h, a2l, 256, wh + 5 * SLOT, wl + 5 * SLOT, ab3, BA, 256, 0, 2, actvh, nullptr };
        GP pt = { t2h, t2l, 256, wh + 2 * SLOT, wl + 2 * SLOT, db3, NTAB, 256, 0, 2, tableh, nullptr };
        layer_kernel<<<nA2 + nT2 + 128, 256, 2 * STAGE_SZ>>>(pa, pt, nA2, nT2, 3, src, E, A);
    }

    // 5) gather
    float* out_a = (float*)d_out;
    float* out_v = (float*)d_out + (size_t)BA * NFEAT;
    gather_kernel<<<A, 256>>>((const uint2*)tableh, (const uint2*)actvh, (const uint2*)xvh,
                              r_ij, dst, out_a, out_v, A);
}

// round 7
// speedup vs baseline: 6.8347x; 1.2252x over previous
#include <cuda_runtime.h>
#include <cuda_fp16.h>
#include <cstdint>

#define NFEAT 64
#define NHID  256
#define EMAX  320000
#define AMAX  10000
#define BAMAX 40000
#define EPS_F 0.1f
#define COEF0 0.31415926535897931f   // pi / R0, R0 = 10
#define NTAB  4096
#define DMAX  10.0f
#define TSCALE ((float)NTAB / DMAX)
#define SLOT  (256 * 256)

// ---------------- scratch (device globals; no allocation allowed) ------------
__device__ __half g_te_h[(size_t)NTAB * 64];
__device__ __half g_te_l[(size_t)NTAB * 64];
__device__ __half g_xa_h[(size_t)BAMAX * 64];
__device__ __half g_xa_l[(size_t)BAMAX * 64];
__device__ __half g_t1h[(size_t)NTAB * NHID];
__device__ __half g_t1l[(size_t)NTAB * NHID];
__device__ __half g_t2h[(size_t)NTAB * NHID];
__device__ __half g_t2l[(size_t)NTAB * NHID];
__device__ __half g_a1h[(size_t)BAMAX * NHID];
__device__ __half g_a1l[(size_t)BAMAX * NHID];
__device__ __half g_a2h[(size_t)BAMAX * NHID];
__device__ __half g_a2l[(size_t)BAMAX * NHID];
__device__ __half g_tableh[(size_t)NTAB * NHID];  // dist MLP lookup fp16, [k][feat][4]
__device__ __half g_actvh[(size_t)BAMAX * NHID];  // actv MLP out fp16, [row][feat][4]
__device__ __half g_xvh[(size_t)BAMAX * 64 * 4];  // x_v packed half4 (v0,v1,v2,0)
__device__ float4 g_ep[EMAX];                     // per-edge (d0,d1,d2,idxf)
__device__ __half g_wh[6 * SLOT];
__device__ __half g_wl[6 * SLOT];
__device__ int g_cnt[AMAX + 1];
__device__ int g_off[AMAX + 1];
__device__ int g_pos[AMAX];
__device__ int g_elist[EMAX];

// ---------------- PTX helpers -------------------------------------------------
__device__ __forceinline__ uint32_t smem_u32(const void* p) {
    uint32_t a;
    asm("{ .reg .u64 t; cvta.to.shared.u64 t, %1; cvt.u32.u64 %0, t; }" : "=r"(a) : "l"(p));
    return a;
}
#define CP16(saddr, gptr) \
    asm volatile("cp.async.cg.shared.global [%0], [%1], 16;" :: "r"(saddr), "l"(gptr) : "memory")
#define CP_COMMIT asm volatile("cp.async.commit_group;" ::: "memory")
#define CP_WAIT0 asm volatile("cp.async.wait_group 0;" ::: "memory")
#define CP_WAIT1 asm volatile("cp.async.wait_group 1;" ::: "memory")

__device__ __forceinline__ void ldsm_x4(uint32_t* r, uint32_t addr) {
    asm volatile("ldmatrix.sync.aligned.m8n8.x4.shared.b16 {%0,%1,%2,%3}, [%4];"
                 : "=r"(r[0]), "=r"(r[1]), "=r"(r[2]), "=r"(r[3]) : "r"(addr));
}
__device__ __forceinline__ void mma16816(float* c, const uint32_t* a, uint32_t b0, uint32_t b1) {
    asm volatile("mma.sync.aligned.m16n8k16.row.col.f32.f16.f16.f32 "
                 "{%0,%1,%2,%3}, {%4,%5,%6,%7}, {%8,%9}, {%0,%1,%2,%3};"
                 : "+f"(c[0]), "+f"(c[1]), "+f"(c[2]), "+f"(c[3])
                 : "r"(a[0]), "r"(a[1]), "r"(a[2]), "r"(a[3]), "r"(b0), "r"(b1));
}
__device__ __forceinline__ void split_h(float v, __half& h, __half& l) {
    h = __float2half_rn(v);
    l = __float2half_rn(v - __half2float(h));
}

// ---------------- prep: tencode + splits + wtrans + xv pack + edge prep + zero
__global__ void prep_kernel(
    const float* __restrict__ x_a, const float* __restrict__ x_v,
    const float* __restrict__ r_ij,
    const float* __restrict__ dW1, const float* __restrict__ dW2, const float* __restrict__ dW3,
    const float* __restrict__ aW1, const float* __restrict__ aW2, const float* __restrict__ aW3,
    int BA, int A, int E)
{
    const int tid = threadIdx.x;
    int bid = blockIdx.x;
    const int S0 = NTAB * 64 / 256;
    const int S1 = (BA * 64) / 256;
    const int SE = (E + 255) / 256;

    if (bid < S0) {
        int t = bid * 256 + tid;
        int k = t >> 6, j = t & 63;
        float d = (float)k * (DMAX / (float)NTAB);
        int kk = j & 31;
        float ph = (float)(1 + (kk >> 1)) * COEF0 * d;
        float v = (j < 32) ? cosf(ph) : sinf(ph);
        __half h, l;
        split_h(v, h, l);
        g_te_h[t] = h; g_te_l[t] = l;
        return;
    }
    bid -= S0;
    if (bid < S1) {
        int t = bid * 256 + tid;
        __half h, l;
        split_h(x_a[t], h, l);
        g_xa_h[t] = h; g_xa_l[t] = l;
        return;
    }
    bid -= S1;
    if (bid < S1) {   // x_v pack: [row][3] fp32 -> half4
        int t = bid * 256 + tid;
        float v0 = x_v[(size_t)t * 3 + 0];
        float v1 = x_v[(size_t)t * 3 + 1];
        float v2 = x_v[(size_t)t * 3 + 2];
        __half2* dst = (__half2*)&g_xvh[(size_t)t * 4];
        dst[0] = __floats2half2_rn(v0, v1);
        dst[1] = __floats2half2_rn(v2, 0.f);
        return;
    }
    bid -= S1;
    if (bid < SE) {   // edge precompute: direction + table index
        int t = bid * 256 + tid;
        if (t < E) {
            float rx = r_ij[(size_t)t * 3 + 0];
            float ry = r_ij[(size_t)t * 3 + 1];
            float rz = r_ij[(size_t)t * 3 + 2];
            float d2s = rx * rx + ry * ry + rz * rz;
            float d = sqrtf(d2s);
            float inv = rsqrtf(EPS_F + d2s);
            float idxf = d * TSCALE;
            if (idxf > (float)(NTAB - 1) - 1e-3f) idxf = (float)(NTAB - 1) - 1e-3f;
            g_ep[t] = make_float4(rx * inv, ry * inv, rz * inv, idxf);
        }
        return;
    }
    bid -= SE;
    if (bid < 1152) {
        const float* W; int K, slot;
        if      (bid < 64)  { W = dW1; K = 64;  slot = 0; }
        else if (bid < 320) { W = dW2; K = 256; slot = 1; bid -= 64; }
        else if (bid < 576) { W = dW3; K = 256; slot = 2; bid -= 320; }
        else if (bid < 640) { W = aW1; K = 64;  slot = 3; bid -= 576; }
        else if (bid < 896) { W = aW2; K = 256; slot = 4; bid -= 640; }
        else                { W = aW3; K = 256; slot = 5; bid -= 896; }
        int t = bid * 256 + tid;
        int n = t & 255, k = t >> 8;
        __half h, l;
        split_h(W[(size_t)k * 256 + n], h, l);
        g_wh[(size_t)slot * SLOT + (size_t)n * K + k] = h;
        g_wl[(size_t)slot * SLOT + (size_t)n * K + k] = l;
        return;
    }
    bid -= 1152;
    int t = bid * 256 + tid;
    if (t <= A) g_cnt[t] = 0;
}

// ---------------- GEMM problem descriptor + body ------------------------------
struct GP {
    const __half* Ahi; const __half* Alo; int lda;
    const __half* Bhi; const __half* Blo;
    const float* bias;
    int M, K, act, mode;       // mode 0: fp16 hi/lo out; 2: fp16 permuted out
    __half* OHi; __half* OLo;
};

#define HBK 32
#define ROWB 80    // 32 halves (64B) + 16B pad
#define A_HI_OFF 0
#define A_LO_OFF 10240
#define B_HI_OFF 20480
#define B_LO_OFF 30720
#define STAGE_SZ 40960

__device__ __forceinline__ void gemm_body(const GP p, int bx, int by) {
    extern __shared__ char smem[];
    const uint32_t sbase = smem_u32(smem);
    const int tid = threadIdx.x;
    const int lane = tid & 31;
    const int wid = tid >> 5;
    const int warp_m = wid & 3;
    const int warp_n = wid >> 2;
    const int row0 = bx * 128;
    const int col0 = by * 128;

    const uint32_t aoff = (uint32_t)(warp_m * 32 + (lane & 15)) * ROWB + ((lane >> 4) << 4);
    const uint32_t boff = (uint32_t)(warp_n * 64 + (lane & 7) + ((lane >> 4) << 3)) * ROWB
                        + (((lane >> 3) & 1) << 4);

    float acc[2][8][4];
#pragma unroll
    for (int tm = 0; tm < 2; tm++)
#pragma unroll
        for (int tn = 0; tn < 8; tn++)
#pragma unroll
            for (int j = 0; j < 4; j++) acc[tm][tn][j] = 0.f;

    const int NC = p.K / HBK;
    const int M = p.M;
    const int lda = p.lda;
    const int K = p.K;

    auto load_stage = [&](int buf, int kb) {
        const uint32_t sb = sbase + buf * STAGE_SZ;
#pragma unroll
        for (int it = 0; it < 2; it++) {
            int idx = tid + it * 256;
            int r = idx >> 2, cs = idx & 3;
            uint32_t so = (uint32_t)r * ROWB + cs * 16;
            size_t ga = (size_t)min(row0 + r, M - 1) * lda + kb + cs * 8;
            CP16(sb + A_HI_OFF + so, p.Ahi + ga);
            CP16(sb + A_LO_OFF + so, p.Alo + ga);
            size_t gb = (size_t)(col0 + r) * K + kb + cs * 8;
            CP16(sb + B_HI_OFF + so, p.Bhi + gb);
            CP16(sb + B_LO_OFF + so, p.Blo + gb);
        }
    };

    load_stage(0, 0);
    CP_COMMIT;
    if (NC > 1) { load_stage(1, HBK); CP_COMMIT; }

    for (int c = 0; c < NC; c++) {
        if (c + 1 < NC) { CP_WAIT1; } else { CP_WAIT0; }
        __syncthreads();
        const uint32_t sb = sbase + (c & 1) * STAGE_SZ;
        const uint32_t abase = sb + aoff;
        const uint32_t bbase = sb + B_HI_OFF + boff;
#pragma unroll
        for (int ks = 0; ks < 2; ks++) {
            uint32_t ah[2][4], al[2][4], bb[4][4];
            ldsm_x4(ah[0], abase + ks * 32);
            ldsm_x4(ah[1], abase + 16 * ROWB + ks * 32);
            ldsm_x4(al[0], abase + A_LO_OFF + ks * 32);
            ldsm_x4(al[1], abase + A_LO_OFF + 16 * ROWB + ks * 32);
#pragma unroll
            for (int tg = 0; tg < 4; tg++)
                ldsm_x4(bb[tg], bbase + tg * 16 * ROWB + ks * 32);
#pragma unroll
            for (int tm = 0; tm < 2; tm++)
#pragma unroll
                for (int tn = 0; tn < 8; tn++) {
                    uint32_t b0 = bb[tn >> 1][(tn & 1) * 2];
                    uint32_t b1 = bb[tn >> 1][(tn & 1) * 2 + 1];
                    mma16816(acc[tm][tn], ah[tm], b0, b1);
                    mma16816(acc[tm][tn], al[tm], b0, b1);
                }
#pragma unroll
            for (int tg = 0; tg < 4; tg++)
                ldsm_x4(bb[tg], bbase + (B_LO_OFF - B_HI_OFF) + tg * 16 * ROWB + ks * 32);
#pragma unroll
            for (int tm = 0; tm < 2; tm++)
#pragma unroll
                for (int tn = 0; tn < 8; tn++) {
                    uint32_t b0 = bb[tn >> 1][(tn & 1) * 2];
                    uint32_t b1 = bb[tn >> 1][(tn & 1) * 2 + 1];
                    mma16816(acc[tm][tn], ah[tm], b0, b1);
                }
        }
        if (c + 2 < NC) {
            __syncthreads();
            load_stage(c & 1, (c + 2) * HBK);
            CP_COMMIT;
        }
    }

#pragma unroll
    for (int tm = 0; tm < 2; tm++)
#pragma unroll
        for (int tn = 0; tn < 8; tn++) {
            int r0 = row0 + warp_m * 32 + tm * 16 + (lane >> 2);
            int col = col0 + warp_n * 64 + tn * 8 + 2 * (lane & 3);
            float b0 = __ldg(&p.bias[col]);
            float b1 = __ldg(&p.bias[col + 1]);
            float v0 = acc[tm][tn][0] + b0;
            float v1 = acc[tm][tn][1] + b1;
            float v2 = acc[tm][tn][2] + b0;
            float v3 = acc[tm][tn][3] + b1;
            if (p.act) {
                v0 = v0 / (1.f + __expf(-v0));
                v1 = v1 / (1.f + __expf(-v1));
                v2 = v2 / (1.f + __expf(-v2));
                v3 = v3 / (1.f + __expf(-v3));
            }
            if (p.mode == 0) {
                __half h0, l0, h1, l1;
                if (r0 < M) {
                    split_h(v0, h0, l0); split_h(v1, h1, l1);
                    *(__half2*)&p.OHi[(size_t)r0 * 256 + col] = __halves2half2(h0, h1);
                    *(__half2*)&p.OLo[(size_t)r0 * 256 + col] = __halves2half2(l0, l1);
                }
                if (r0 + 8 < M) {
                    split_h(v2, h0, l0); split_h(v3, h1, l1);
                    *(__half2*)&p.OHi[(size_t)(r0 + 8) * 256 + col] = __halves2half2(h0, h1);
                    *(__half2*)&p.OLo[(size_t)(r0 + 8) * 256 + col] = __halves2half2(l0, l1);
                }
            } else {
                int pc0 = ((col & 63) << 2) | (col >> 6);
                int pc1 = (((col + 1) & 63) << 2) | ((col + 1) >> 6);
                if (r0 < M) {
                    p.OHi[(size_t)r0 * 256 + pc0] = __float2half_rn(v0);
                    p.OHi[(size_t)r0 * 256 + pc1] = __float2half_rn(v1);
                }
                if (r0 + 8 < M) {
                    p.OHi[(size_t)(r0 + 8) * 256 + pc0] = __float2half_rn(v2);
                    p.OHi[(size_t)(r0 + 8) * 256 + pc1] = __float2half_rn(v3);
                }
            }
        }
}

// ---------------- single-block exclusive scan (device body) -------------------
__device__ void scan_body(int A) {
    __shared__ int sh[256];
    int tid = threadIdx.x;
    int chunk = (A + 255) >> 8;
    int base = tid * chunk;
    int sum = 0;
    for (int j = 0; j < chunk; j++) {
        int idx = base + j;
        if (idx < A) sum += g_cnt[idx];
    }
    sh[tid] = sum;
    __syncthreads();
    for (int off = 1; off < 256; off <<= 1) {
        int v = 0;
        if (tid >= off) v = sh[tid - off];
        __syncthreads();
        sh[tid] += v;
        __syncthreads();
    }
    int run = (tid == 0) ? 0 : sh[tid - 1];
    for (int j = 0; j < chunk; j++) {
        int idx = base + j;
        if (idx < A) {
            g_off[idx] = run;
            g_pos[idx] = run;
            run += g_cnt[idx];
        }
    }
    if (base < A && A <= base + chunk) g_off[A] = run;
}

// ---------------- merged layer kernel: 2 GEMM problems + sort-step aux CTAs ---
__global__ void __launch_bounds__(256, 2) layer_kernel(
    GP pa, GP pt, int nA2, int nT2,
    int aux, const int* __restrict__ src, int E, int A)
{
    int bid = blockIdx.x;
    const int nG = nA2 + nT2;
    if (bid < nG) {
        bool isA = bid < nA2;
        GP p = isA ? pa : pt;
        int lb = isA ? bid : bid - nA2;
        gemm_body(p, lb >> 1, lb & 1);
        return;
    }
    int abid = bid - nG;
    int tid = threadIdx.x;
    if (aux == 1) {
        for (int t = abid * 256 + tid; t < E; t += 128 * 256)
            atomicAdd(&g_cnt[src[t]], 1);
    } else if (aux == 2) {
        scan_body(A);
    } else if (aux == 3) {
        for (int t = abid * 256 + tid; t < E; t += 128 * 256) {
            int pp = atomicAdd(&g_pos[src[t]], 1);
            g_elist[pp] = t;
        }
    }
}

// ---------------- per-atom gather: precomputed edge dir/idx + fp16 rows -------
__global__ __launch_bounds__(256) void gather_kernel(
    const uint2* __restrict__ T4,           // g_tableh: [k][feat] 4 halves
    const uint2* __restrict__ P4,           // g_actvh: [row][feat] 4 halves
    const uint2* __restrict__ XV,           // g_xvh: [row*64+f] 4 halves
    const float4* __restrict__ EP,          // per-edge (d0,d1,d2,idxf)
    const int* __restrict__ dst,
    float* __restrict__ out_a, float* __restrict__ out_v, int A)
{
    int a = blockIdx.x;
    int f = threadIdx.x & 63;
    int b = threadIdx.x >> 6;
    int p0 = g_off[a];
    int p1 = g_off[a + 1];

    float av0 = 0.f, av1 = 0.f, av2 = 0.f, aa = 0.f;
#pragma unroll 2
    for (int p = p0; p < p1; ++p) {
        int e = g_elist[p];
        float4 ed = __ldg(&EP[e]);
        float d0 = ed.x, d1 = ed.y, d2 = ed.z;
        int k = (int)ed.w;
        float w = ed.w - (float)k;

        uint2 t0u = __ldg(&T4[(size_t)k * 64 + f]);
        uint2 t1u = __ldg(&T4[(size_t)(k + 1) * 64 + f]);
        float2 t0a = __half22float2(*(__half2*)&t0u.x);
        float2 t0b = __half22float2(*(__half2*)&t0u.y);
        float2 t1a = __half22float2(*(__half2*)&t1u.x);
        float2 t1b = __half22float2(*(__half2*)&t1u.y);
        float q0 = fmaf(w, t1a.x - t0a.x, t0a.x);
        float q1 = fmaf(w, t1a.y - t0a.y, t0a.y);
        float q2 = fmaf(w, t1b.x - t0b.x, t0b.x);
        float q3 = fmaf(w, t1b.y - t0b.y, t0b.y);

        int dd = __ldg(&dst[e]);
        size_t ridx = (size_t)(b * A + dd) * 64 + f;
        uint2 pr = __ldg(&P4[ridx]);
        __half2 pra = *(__half2*)&pr.x;
        __half2 prb = *(__half2*)&pr.y;
        q0 *= __low2float(pra);
        q1 *= __high2float(pra);
        q2 *= __low2float(prb);
        q3 *= __high2float(prb);

        uint2 vr = __ldg(&XV[ridx]);
        float2 va = __half22float2(*(__half2*)&vr.x);
        float v2f = __low2float(*(__half2*)&vr.y);
        float v0 = va.x, v1 = va.y, v2 = v2f;
        float c0 = v1 * d2 - v2 * d1;
        float c1 = v2 * d0 - v0 * d2;
        float c2 = v0 * d1 - v1 * d0;
        av0 += v0 * q0 + c0 * q1 + d0 * q2;
        av1 += v1 * q0 + c1 * q1 + d1 * q2;
        av2 += v2 * q0 + c2 * q1 + d2 * q2;
        aa  += q3;
    }
    out_a[(size_t)(b * A + a) * 64 + f] = aa;
    float* OV = out_v + (size_t)((b * A + a) * 64 + f) * 3;
    OV[0] = av0;
    OV[1] = av1;
    OV[2] = av2;
}

// ---------------- launch ------------------------------------------------------
extern "C" void kernel_launch(void* const* d_in, const int* in_sizes, int n_in,
                              void* d_out, int out_size) {
    const float* x_a  = (const float*)d_in[0];
    const float* x_v  = (const float*)d_in[1];
    const float* r_ij = (const float*)d_in[2];
    const int*   src  = (const int*)d_in[3];
    const int*   dst  = (const int*)d_in[4];
    const float* dW1 = (const float*)d_in[5];
    const float* db1 = (const float*)d_in[6];
    const float* dW2 = (const float*)d_in[7];
    const float* db2 = (const float*)d_in[8];
    const float* dW3 = (const float*)d_in[9];
    const float* db3 = (const float*)d_in[10];
    const float* aW1 = (const float*)d_in[11];
    const float* ab1 = (const float*)d_in[12];
    const float* aW2 = (const float*)d_in[13];
    const float* ab2 = (const float*)d_in[14];
    const float* aW3 = (const float*)d_in[15];
    const float* ab3 = (const float*)d_in[16];

    const int E  = in_sizes[3];
    const int BA = in_sizes[0] / NFEAT;
    const int A  = BA / 4;                 // B = 4

    __half *te_h, *te_l, *xa_h, *xa_l;
    __half *t1h, *t1l, *t2h, *t2l, *a1h, *a1l, *a2h, *a2l;
    __half *wh, *wl, *actvh, *tableh, *xvh;
    float4 *ep;
    cudaGetSymbolAddress((void**)&te_h, g_te_h);
    cudaGetSymbolAddress((void**)&te_l, g_te_l);
    cudaGetSymbolAddress((void**)&xa_h, g_xa_h);
    cudaGetSymbolAddress((void**)&xa_l, g_xa_l);
    cudaGetSymbolAddress((void**)&t1h, g_t1h);
    cudaGetSymbolAddress((void**)&t1l, g_t1l);
    cudaGetSymbolAddress((void**)&t2h, g_t2h);
    cudaGetSymbolAddress((void**)&t2l, g_t2l);
    cudaGetSymbolAddress((void**)&a1h, g_a1h);
    cudaGetSymbolAddress((void**)&a1l, g_a1l);
    cudaGetSymbolAddress((void**)&a2h, g_a2h);
    cudaGetSymbolAddress((void**)&a2l, g_a2l);
    cudaGetSymbolAddress((void**)&wh, g_wh);
    cudaGetSymbolAddress((void**)&wl, g_wl);
    cudaGetSymbolAddress((void**)&tableh, g_tableh);
    cudaGetSymbolAddress((void**)&actvh, g_actvh);
    cudaGetSymbolAddress((void**)&xvh, g_xvh);
    cudaGetSymbolAddress((void**)&ep, g_ep);

    cudaFuncSetAttribute(layer_kernel, cudaFuncAttributeMaxDynamicSharedMemorySize, 2 * STAGE_SZ);

    // 1) prep
    const int S1 = (BA * 64) / 256;
    const int SE = (E + 255) / 256;
    const int prep_blocks = (NTAB * 64 / 256) + 2 * S1 + SE + 1152 + (A + 1 + 255) / 256;
    prep_kernel<<<prep_blocks, 256>>>(x_a, x_v, r_ij, dW1, dW2, dW3, aW1, aW2, aW3, BA, A, E);

    const int nA2 = 2 * ((BA + 127) / 128);
    const int nT2 = 2 * (NTAB / 128);

    // 2) layer 1 (K=64) + hist
    {
        GP pa = { xa_h, xa_l, 64, wh + 3 * SLOT, wl + 3 * SLOT, ab1, BA, 64, 1, 0, a1h, a1l };
        GP pt = { te_h, te_l, 64, wh + 0 * SLOT, wl + 0 * SLOT, db1, NTAB, 64, 1, 0, t1h, t1l };
        layer_kernel<<<nA2 + nT2 + 128, 256, 2 * STAGE_SZ>>>(pa, pt, nA2, nT2, 1, src, E, A);
    }
    // 3) layer 2 (K=256) + scan
    {
        GP pa = { a1h, a1l, 256, wh + 4 * SLOT, wl + 4 * SLOT, ab2, BA, 256, 1, 0, a2h, a2l };
        GP pt = { t1h, t1l, 256, wh + 1 * SLOT, wl + 1 * SLOT, db2, NTAB, 256, 1, 0, t2h, t2l };
        layer_kernel<<<nA2 + nT2 + 1, 256, 2 * STAGE_SZ>>>(pa, pt, nA2, nT2, 2, src, E, A);
    }
    // 4) layer 3 (K=256, no act, fp16 permuted outs) + scatter
    {
        GP pa = { a2h, a2l, 256, wh + 5 * SLOT, wl + 5 * SLOT, ab3, BA, 256, 0, 2, actvh, nullptr };
        GP pt = { t2h, t2l, 256, wh + 2 * SLOT, wl + 2 * SLOT, db3, NTAB, 256, 0, 2, tableh, nullptr };
        layer_kernel<<<nA2 + nT2 + 128, 256, 2 * STAGE_SZ>>>(pa, pt, nA2, nT2, 3, src, E, A);
    }

    // 5) gather
    float* out_a = (float*)d_out;
    float* out_v = (float*)d_out + (size_t)BA * NFEAT;
    gather_kernel<<<A, 256>>>((const uint2*)tableh, (const uint2*)actvh, (const uint2*)xvh,
                              (const float4*)ep, dst, out_a, out_v, A);
}

// round 8
// speedup vs baseline: 7.2224x; 1.0567x over previous
#include <cuda_runtime.h>
#include <cuda_fp16.h>
#include <cstdint>

#define NFEAT 64
#define NHID  256
#define EMAX  320000
#define AMAX  10000
#define BAMAX 40000
#define EPS_F 0.1f
#define COEF0 0.31415926535897931f   // pi / R0, R0 = 10
#define NTAB  4096
#define DMAX  10.0f
#define TSCALE ((float)NTAB / DMAX)
#define SLOT  (256 * 256)

// ---------------- scratch (device globals; no allocation allowed) ------------
__device__ __half g_te_h[(size_t)NTAB * 64];
__device__ __half g_te_l[(size_t)NTAB * 64];
__device__ __half g_xa_h[(size_t)BAMAX * 64];
__device__ __half g_xa_l[(size_t)BAMAX * 64];
__device__ __half g_t1h[(size_t)NTAB * NHID];
__device__ __half g_t1l[(size_t)NTAB * NHID];
__device__ __half g_t2h[(size_t)NTAB * NHID];
__device__ __half g_t2l[(size_t)NTAB * NHID];
__device__ __half g_a1h[(size_t)BAMAX * NHID];
__device__ __half g_a1l[(size_t)BAMAX * NHID];
__device__ __half g_a2h[(size_t)BAMAX * NHID];
__device__ __half g_a2l[(size_t)BAMAX * NHID];
__device__ __half g_tableh[(size_t)NTAB * NHID];  // dist MLP lookup fp16, [k][feat][4]
__device__ __half g_actvh[(size_t)BAMAX * NHID];  // actv MLP out fp16, [row][feat][4]
__device__ __half g_xvh[(size_t)BAMAX * 64 * 4];  // x_v packed half4 (v0,v1,v2,0)
__device__ float4 g_ep[EMAX];                     // per-edge (d0,d1,d2,idxf)
__device__ __half g_wh[6 * SLOT];                 // transposed weight hi only
__device__ int g_cnt[AMAX + 1];
__device__ int g_off[AMAX + 1];
__device__ int g_pos[AMAX];
__device__ int g_elist[EMAX];

// ---------------- PTX helpers -------------------------------------------------
__device__ __forceinline__ uint32_t smem_u32(const void* p) {
    uint32_t a;
    asm("{ .reg .u64 t; cvta.to.shared.u64 t, %1; cvt.u32.u64 %0, t; }" : "=r"(a) : "l"(p));
    return a;
}
#define CP16(saddr, gptr) \
    asm volatile("cp.async.cg.shared.global [%0], [%1], 16;" :: "r"(saddr), "l"(gptr) : "memory")
#define CP_COMMIT asm volatile("cp.async.commit_group;" ::: "memory")
#define CP_WAIT0 asm volatile("cp.async.wait_group 0;" ::: "memory")
#define CP_WAIT1 asm volatile("cp.async.wait_group 1;" ::: "memory")
#define CP_WAIT2 asm volatile("cp.async.wait_group 2;" ::: "memory")

__device__ __forceinline__ void ldsm_x4(uint32_t* r, uint32_t addr) {
    asm volatile("ldmatrix.sync.aligned.m8n8.x4.shared.b16 {%0,%1,%2,%3}, [%4];"
                 : "=r"(r[0]), "=r"(r[1]), "=r"(r[2]), "=r"(r[3]) : "r"(addr));
}
__device__ __forceinline__ void mma16816(float* c, const uint32_t* a, uint32_t b0, uint32_t b1) {
    asm volatile("mma.sync.aligned.m16n8k16.row.col.f32.f16.f16.f32 "
                 "{%0,%1,%2,%3}, {%4,%5,%6,%7}, {%8,%9}, {%0,%1,%2,%3};"
                 : "+f"(c[0]), "+f"(c[1]), "+f"(c[2]), "+f"(c[3])
                 : "r"(a[0]), "r"(a[1]), "r"(a[2]), "r"(a[3]), "r"(b0), "r"(b1));
}
__device__ __forceinline__ void split_h(float v, __half& h, __half& l) {
    h = __float2half_rn(v);
    l = __float2half_rn(v - __half2float(h));
}

// ---------------- prep: tencode + splits + wtrans + xv pack + edge prep + zero
__global__ void prep_kernel(
    const float* __restrict__ x_a, const float* __restrict__ x_v,
    const float* __restrict__ r_ij,
    const float* __restrict__ dW1, const float* __restrict__ dW2, const float* __restrict__ dW3,
    const float* __restrict__ aW1, const float* __restrict__ aW2, const float* __restrict__ aW3,
    int BA, int A, int E)
{
    const int tid = threadIdx.x;
    int bid = blockIdx.x;
    const int S0 = NTAB * 64 / 256;
    const int S1 = (BA * 64) / 256;
    const int SE = (E + 255) / 256;

    if (bid < S0) {
        int t = bid * 256 + tid;
        int k = t >> 6, j = t & 63;
        float d = (float)k * (DMAX / (float)NTAB);
        int kk = j & 31;
        float ph = (float)(1 + (kk >> 1)) * COEF0 * d;
        float v = (j < 32) ? cosf(ph) : sinf(ph);
        __half h, l;
        split_h(v, h, l);
        g_te_h[t] = h; g_te_l[t] = l;
        return;
    }
    bid -= S0;
    if (bid < S1) {
        int t = bid * 256 + tid;
        __half h, l;
        split_h(x_a[t], h, l);
        g_xa_h[t] = h; g_xa_l[t] = l;
        return;
    }
    bid -= S1;
    if (bid < S1) {   // x_v pack: [row][3] fp32 -> half4
        int t = bid * 256 + tid;
        float v0 = x_v[(size_t)t * 3 + 0];
        float v1 = x_v[(size_t)t * 3 + 1];
        float v2 = x_v[(size_t)t * 3 + 2];
        __half2* dst = (__half2*)&g_xvh[(size_t)t * 4];
        dst[0] = __floats2half2_rn(v0, v1);
        dst[1] = __floats2half2_rn(v2, 0.f);
        return;
    }
    bid -= S1;
    if (bid < SE) {   // edge precompute: direction + table index
        int t = bid * 256 + tid;
        if (t < E) {
            float rx = r_ij[(size_t)t * 3 + 0];
            float ry = r_ij[(size_t)t * 3 + 1];
            float rz = r_ij[(size_t)t * 3 + 2];
            float d2s = rx * rx + ry * ry + rz * rz;
            float d = sqrtf(d2s);
            float inv = rsqrtf(EPS_F + d2s);
            float idxf = d * TSCALE;
            if (idxf > (float)(NTAB - 1) - 1e-3f) idxf = (float)(NTAB - 1) - 1e-3f;
            g_ep[t] = make_float4(rx * inv, ry * inv, rz * inv, idxf);
        }
        return;
    }
    bid -= SE;
    if (bid < 1152) {
        const float* W; int K, slot;
        if      (bid < 64)  { W = dW1; K = 64;  slot = 0; }
        else if (bid < 320) { W = dW2; K = 256; slot = 1; bid -= 64; }
        else if (bid < 576) { W = dW3; K = 256; slot = 2; bid -= 320; }
        else if (bid < 640) { W = aW1; K = 64;  slot = 3; bid -= 576; }
        else if (bid < 896) { W = aW2; K = 256; slot = 4; bid -= 640; }
        else                { W = aW3; K = 256; slot = 5; bid -= 896; }
        int t = bid * 256 + tid;
        int n = t & 255, k = t >> 8;
        g_wh[(size_t)slot * SLOT + (size_t)n * K + k] =
            __float2half_rn(W[(size_t)k * 256 + n]);
        return;
    }
    bid -= 1152;
    int t = bid * 256 + tid;
    if (t <= A) g_cnt[t] = 0;
}

// ---------------- GEMM problem descriptor + body ------------------------------
struct GP {
    const __half* Ahi; const __half* Alo; int lda;
    const __half* Bhi;
    const float* bias;
    int M, K, act, mode;       // mode 0: fp16 hi/lo out; 2: fp16 permuted out
    __half* OHi; __half* OLo;
};

#define HBK 32
#define ROWB 80    // 32 halves (64B) + 16B pad
#define A_HI_OFF 0
#define A_LO_OFF 10240
#define B_HI_OFF 20480
#define STAGE_SZ 30720

__device__ __forceinline__ void gemm_body(const GP p, int bx, int by) {
    extern __shared__ char smem[];
    const uint32_t sbase = smem_u32(smem);
    const int tid = threadIdx.x;
    const int lane = tid & 31;
    const int wid = tid >> 5;
    const int warp_m = wid & 3;
    const int warp_n = wid >> 2;
    const int row0 = bx * 128;
    const int col0 = by * 128;

    const uint32_t aoff = (uint32_t)(warp_m * 32 + (lane & 15)) * ROWB + ((lane >> 4) << 4);
    const uint32_t boff = (uint32_t)(warp_n * 64 + (lane & 7) + ((lane >> 4) << 3)) * ROWB
                        + (((lane >> 3) & 1) << 4);

    float acc[2][8][4];
#pragma unroll
    for (int tm = 0; tm < 2; tm++)
#pragma unroll
        for (int tn = 0; tn < 8; tn++)
#pragma unroll
            for (int j = 0; j < 4; j++) acc[tm][tn][j] = 0.f;

    const int NC = p.K / HBK;
    const int M = p.M;
    const int lda = p.lda;
    const int K = p.K;

    auto load_stage = [&](int buf, int kb) {
        const uint32_t sb = sbase + buf * STAGE_SZ;
#pragma unroll
        for (int it = 0; it < 2; it++) {
            int idx = tid + it * 256;
            int r = idx >> 2, cs = idx & 3;
            uint32_t so = (uint32_t)r * ROWB + cs * 16;
            size_t ga = (size_t)min(row0 + r, M - 1) * lda + kb + cs * 8;
            CP16(sb + A_HI_OFF + so, p.Ahi + ga);
            CP16(sb + A_LO_OFF + so, p.Alo + ga);
            size_t gb = (size_t)(col0 + r) * K + kb + cs * 8;
            CP16(sb + B_HI_OFF + so, p.Bhi + gb);
        }
    };

    // 3-stage pipeline
    load_stage(0, 0);
    CP_COMMIT;
    if (NC > 1) { load_stage(1, HBK); CP_COMMIT; }

    for (int c = 0; c < NC; c++) {
        if (c + 2 < NC) {
            __syncthreads();          // all warps done reading buf (c-1)%3
            load_stage((c + 2) % 3, (c + 2) * HBK);
            CP_COMMIT;
        }
        int pend = NC - 1 - c;
        if (pend >= 2)      { CP_WAIT2; }
        else if (pend == 1) { CP_WAIT1; }
        else                { CP_WAIT0; }
        __syncthreads();
        const uint32_t sb = sbase + (c % 3) * STAGE_SZ;
        const uint32_t abase = sb + aoff;
        const uint32_t bbase = sb + B_HI_OFF + boff;
#pragma unroll
        for (int ks = 0; ks < 2; ks++) {
            uint32_t ah[2][4], al[2][4], bb[4][4];
            ldsm_x4(ah[0], abase + ks * 32);
            ldsm_x4(ah[1], abase + 16 * ROWB + ks * 32);
            ldsm_x4(al[0], abase + A_LO_OFF + ks * 32);
            ldsm_x4(al[1], abase + A_LO_OFF + 16 * ROWB + ks * 32);
#pragma unroll
            for (int tg = 0; tg < 4; tg++)
                ldsm_x4(bb[tg], bbase + tg * 16 * ROWB + ks * 32);
#pragma unroll
            for (int tm = 0; tm < 2; tm++)
#pragma unroll
                for (int tn = 0; tn < 8; tn++) {
                    uint32_t b0 = bb[tn >> 1][(tn & 1) * 2];
                    uint32_t b1 = bb[tn >> 1][(tn & 1) * 2 + 1];
                    mma16816(acc[tm][tn], ah[tm], b0, b1);
                    mma16816(acc[tm][tn], al[tm], b0, b1);
                }
        }
    }

#pragma unroll
    for (int tm = 0; tm < 2; tm++)
#pragma unroll
        for (int tn = 0; tn < 8; tn++) {
            int r0 = row0 + warp_m * 32 + tm * 16 + (lane >> 2);
            int col = col0 + warp_n * 64 + tn * 8 + 2 * (lane & 3);
            float b0 = __ldg(&p.bias[col]);
            float b1 = __ldg(&p.bias[col + 1]);
            float v0 = acc[tm][tn][0] + b0;
            float v1 = acc[tm][tn][1] + b1;
            float v2 = acc[tm][tn][2] + b0;
            float v3 = acc[tm][tn][3] + b1;
            if (p.act) {
                v0 = v0 / (1.f + __expf(-v0));
                v1 = v1 / (1.f + __expf(-v1));
                v2 = v2 / (1.f + __expf(-v2));
                v3 = v3 / (1.f + __expf(-v3));
            }
            if (p.mode == 0) {
                __half h0, l0, h1, l1;
                if (r0 < M) {
                    split_h(v0, h0, l0); split_h(v1, h1, l1);
                    *(__half2*)&p.OHi[(size_t)r0 * 256 + col] = __halves2half2(h0, h1);
                    *(__half2*)&p.OLo[(size_t)r0 * 256 + col] = __halves2half2(l0, l1);
                }
                if (r0 + 8 < M) {
                    split_h(v2, h0, l0); split_h(v3, h1, l1);
                    *(__half2*)&p.OHi[(size_t)(r0 + 8) * 256 + col] = __halves2half2(h0, h1);
                    *(__half2*)&p.OLo[(size_t)(r0 + 8) * 256 + col] = __halves2half2(l0, l1);
                }
            } else {
                int pc0 = ((col & 63) << 2) | (col >> 6);
                int pc1 = (((col + 1) & 63) << 2) | ((col + 1) >> 6);
                if (r0 < M) {
                    p.OHi[(size_t)r0 * 256 + pc0] = __float2half_rn(v0);
                    p.OHi[(size_t)r0 * 256 + pc1] = __float2half_rn(v1);
                }
                if (r0 + 8 < M) {
                    p.OHi[(size_t)(r0 + 8) * 256 + pc0] = __float2half_rn(v2);
                    p.OHi[(size_t)(r0 + 8) * 256 + pc1] = __float2half_rn(v3);
                }
            }
        }
}

// ---------------- single-block exclusive scan (device body) -------------------
__device__ void scan_body(int A) {
    __shared__ int sh[256];
    int tid = threadIdx.x;
    int chunk = (A + 255) >> 8;
    int base = tid * chunk;
    int sum = 0;
    for (int j = 0; j < chunk; j++) {
        int idx = base + j;
        if (idx < A) sum += g_cnt[idx];
    }
    sh[tid] = sum;
    __syncthreads();
    for (int off = 1; off < 256; off <<= 1) {
        int v = 0;
        if (tid >= off) v = sh[tid - off];
        __syncthreads();
        sh[tid] += v;
        __syncthreads();
    }
    int run = (tid == 0) ? 0 : sh[tid - 1];
    for (int j = 0; j < chunk; j++) {
        int idx = base + j;
        if (idx < A) {
            g_off[idx] = run;
            g_pos[idx] = run;
            run += g_cnt[idx];
        }
    }
    if (base < A && A <= base + chunk) g_off[A] = run;
}

// ---------------- merged layer kernel: 2 GEMM problems + sort-step aux CTAs ---
__global__ void __launch_bounds__(256, 2) layer_kernel(
    GP pa, GP pt, int nA2, int nT2,
    int aux, const int* __restrict__ src, int E, int A)
{
    int bid = blockIdx.x;
    const int nG = nA2 + nT2;
    if (bid < nG) {
        bool isA = bid < nA2;
        GP p = isA ? pa : pt;
        int lb = isA ? bid : bid - nA2;
        gemm_body(p, lb >> 1, lb & 1);
        return;
    }
    int abid = bid - nG;
    int tid = threadIdx.x;
    if (aux == 1) {
        for (int t = abid * 256 + tid; t < E; t += 128 * 256)
            atomicAdd(&g_cnt[src[t]], 1);
    } else if (aux == 2) {
        scan_body(A);
    } else if (aux == 3) {
        for (int t = abid * 256 + tid; t < E; t += 128 * 256) {
            int pp = atomicAdd(&g_pos[src[t]], 1);
            g_elist[pp] = t;
        }
    }
}

// ---------------- per-atom gather: precomputed edge dir/idx + fp16 rows -------
__global__ __launch_bounds__(256) void gather_kernel(
    const uint2* __restrict__ T4,           // g_tableh: [k][feat] 4 halves
    const uint2* __restrict__ P4,           // g_actvh: [row][feat] 4 halves
    const uint2* __restrict__ XV,           // g_xvh: [row*64+f] 4 halves
    const float4* __restrict__ EP,          // per-edge (d0,d1,d2,idxf)
    const int* __restrict__ dst,
    float* __restrict__ out_a, float* __restrict__ out_v, int A)
{
    int a = blockIdx.x;
    int f = threadIdx.x & 63;
    int b = threadIdx.x >> 6;
    int p0 = g_off[a];
    int p1 = g_off[a + 1];

    float av0 = 0.f, av1 = 0.f, av2 = 0.f, aa = 0.f;
#pragma unroll 2
    for (int p = p0; p < p1; ++p) {
        int e = g_elist[p];
        float4 ed = __ldg(&EP[e]);
        float d0 = ed.x, d1 = ed.y, d2 = ed.z;
        int k = (int)ed.w;
        float w = ed.w - (float)k;

        uint2 t0u = __ldg(&T4[(size_t)k * 64 + f]);
        uint2 t1u = __ldg(&T4[(size_t)(k + 1) * 64 + f]);
        float2 t0a = __half22float2(*(__half2*)&t0u.x);
        float2 t0b = __half22float2(*(__half2*)&t0u.y);
        float2 t1a = __half22float2(*(__half2*)&t1u.x);
        float2 t1b = __half22float2(*(__half2*)&t1u.y);
        float q0 = fmaf(w, t1a.x - t0a.x, t0a.x);
        float q1 = fmaf(w, t1a.y - t0a.y, t0a.y);
        float q2 = fmaf(w, t1b.x - t0b.x, t0b.x);
        float q3 = fmaf(w, t1b.y - t0b.y, t0b.y);

        int dd = __ldg(&dst[e]);
        size_t ridx = (size_t)(b * A + dd) * 64 + f;
        uint2 pr = __ldg(&P4[ridx]);
        __half2 pra = *(__half2*)&pr.x;
        __half2 prb = *(__half2*)&pr.y;
        q0 *= __low2float(pra);
        q1 *= __high2float(pra);
        q2 *= __low2float(prb);
        q3 *= __high2float(prb);

        uint2 vr = __ldg(&XV[ridx]);
        float2 va = __half22float2(*(__half2*)&vr.x);
        float v2f = __low2float(*(__half2*)&vr.y);
        float v0 = va.x, v1 = va.y, v2 = v2f;
        float c0 = v1 * d2 - v2 * d1;
        float c1 = v2 * d0 - v0 * d2;
        float c2 = v0 * d1 - v1 * d0;
        av0 += v0 * q0 + c0 * q1 + d0 * q2;
        av1 += v1 * q0 + c1 * q1 + d1 * q2;
        av2 += v2 * q0 + c2 * q1 + d2 * q2;
        aa  += q3;
    }
    out_a[(size_t)(b * A + a) * 64 + f] = aa;
    float* OV = out_v + (size_t)((b * A + a) * 64 + f) * 3;
    OV[0] = av0;
    OV[1] = av1;
    OV[2] = av2;
}

// ---------------- launch ------------------------------------------------------
extern "C" void kernel_launch(void* const* d_in, const int* in_sizes, int n_in,
                              void* d_out, int out_size) {
    const float* x_a  = (const float*)d_in[0];
    const float* x_v  = (const float*)d_in[1];
    const float* r_ij = (const float*)d_in[2];
    const int*   src  = (const int*)d_in[3];
    const int*   dst  = (const int*)d_in[4];
    const float* dW1 = (const float*)d_in[5];
    const float* db1 = (const float*)d_in[6];
    const float* dW2 = (const float*)d_in[7];
    const float* db2 = (const float*)d_in[8];
    const float* dW3 = (const float*)d_in[9];
    const float* db3 = (const float*)d_in[10];
    const float* aW1 = (const float*)d_in[11];
    const float* ab1 = (const float*)d_in[12];
    const float* aW2 = (const float*)d_in[13];
    const float* ab2 = (const float*)d_in[14];
    const float* aW3 = (const float*)d_in[15];
    const float* ab3 = (const float*)d_in[16];

    const int E  = in_sizes[3];
    const int BA = in_sizes[0] / NFEAT;
    const int A  = BA / 4;                 // B = 4

    __half *te_h, *te_l, *xa_h, *xa_l;
    __half *t1h, *t1l, *t2h, *t2l, *a1h, *a1l, *a2h, *a2l;
    __half *wh, *actvh, *tableh, *xvh;
    float4 *ep;
    cudaGetSymbolAddress((void**)&te_h, g_te_h);
    cudaGetSymbolAddress((void**)&te_l, g_te_l);
    cudaGetSymbolAddress((void**)&xa_h, g_xa_h);
    cudaGetSymbolAddress((void**)&xa_l, g_xa_l);
    cudaGetSymbolAddress((void**)&t1h, g_t1h);
    cudaGetSymbolAddress((void**)&t1l, g_t1l);
    cudaGetSymbolAddress((void**)&t2h, g_t2h);
    cudaGetSymbolAddress((void**)&t2l, g_t2l);
    cudaGetSymbolAddress((void**)&a1h, g_a1h);
    cudaGetSymbolAddress((void**)&a1l, g_a1l);
    cudaGetSymbolAddress((void**)&a2h, g_a2h);
    cudaGetSymbolAddress((void**)&a2l, g_a2l);
    cudaGetSymbolAddress((void**)&wh, g_wh);
    cudaGetSymbolAddress((void**)&tableh, g_tableh);
    cudaGetSymbolAddress((void**)&actvh, g_actvh);
    cudaGetSymbolAddress((void**)&xvh, g_xvh);
    cudaGetSymbolAddress((void**)&ep, g_ep);

    cudaFuncSetAttribute(layer_kernel, cudaFuncAttributeMaxDynamicSharedMemorySize, 3 * STAGE_SZ);

    // 1) prep
    const int S1 = (BA * 64) / 256;
    const int SE = (E + 255) / 256;
    const int prep_blocks = (NTAB * 64 / 256) + 2 * S1 + SE + 1152 + (A + 1 + 255) / 256;
    prep_kernel<<<prep_blocks, 256>>>(x_a, x_v, r_ij, dW1, dW2, dW3, aW1, aW2, aW3, BA, A, E);

    const int nA2 = 2 * ((BA + 127) / 128);
    const int nT2 = 2 * (NTAB / 128);

    // 2) layer 1 (K=64) + hist
    {
        GP pa = { xa_h, xa_l, 64, wh + 3 * SLOT, ab1, BA, 64, 1, 0, a1h, a1l };
        GP pt = { te_h, te_l, 64, wh + 0 * SLOT, db1, NTAB, 64, 1, 0, t1h, t1l };
        layer_kernel<<<nA2 + nT2 + 128, 256, 3 * STAGE_SZ>>>(pa, pt, nA2, nT2, 1, src, E, A);
    }
    // 3) layer 2 (K=256) + scan
    {
        GP pa = { a1h, a1l, 256, wh + 4 * SLOT, ab2, BA, 256, 1, 0, a2h, a2l };
        GP pt = { t1h, t1l, 256, wh + 1 * SLOT, db2, NTAB, 256, 1, 0, t2h, t2l };
        layer_kernel<<<nA2 + nT2 + 1, 256, 3 * STAGE_SZ>>>(pa, pt, nA2, nT2, 2, src, E, A);
    }
    // 4) layer 3 (K=256, no act, fp16 permuted outs) + scatter
    {
        GP pa = { a2h, a2l, 256, wh + 5 * SLOT, ab3, BA, 256, 0, 2, actvh, nullptr };
        GP pt = { t2h, t2l, 256, wh + 2 * SLOT, db3, NTAB, 256, 0, 2, tableh, nullptr };
        layer_kernel<<<nA2 + nT2 + 128, 256, 3 * STAGE_SZ>>>(pa, pt, nA2, nT2, 3, src, E, A);
    }

    // 5) gather
    float* out_a = (float*)d_out;
    float* out_v = (float*)d_out + (size_t)BA * NFEAT;
    gather_kernel<<<A, 256>>>((const uint2*)tableh, (const uint2*)actvh, (const uint2*)xvh,
                              (const float4*)ep, dst, out_a, out_v, A);
}